// round 3
// baseline (speedup 1.0000x reference)
#include <cuda_runtime.h>
#include <math.h>

#define EPS 1e-5f
#define CC 64
#define NN 8
#define HW 65536
#define P1 128
#define NB1 (HW/P1)      /* 512 */
#define CH25 1024
#define NB25 (HW/CH25)   /* 64 */
#define P3 256
#define NB3 (HW/P3)      /* 256 */

// ---------------- scratch (__device__ globals; no allocation) ----------------
__device__ float g_val[(size_t)2*NN*HW*CC];   // 256 MiB, layout [side][n][pix][c]
__device__ float g_k[2*NN*HW];                // silu'd key values
__device__ float g_psum[2*NN*NB1*CC];
__device__ float g_pmax[2*NN*NB1*CC];
__device__ float g_pkm[2*NN*NB1];
__device__ float g_pkz[2*NN*NB1];
__device__ float g_avg[2*NN*CC];
__device__ float g_mx[2*NN*CC];
__device__ float g_kM[2*NN];
__device__ float g_kZ[2*NN];
__device__ float g_feap[2*NN*NB25*CC];
__device__ float g_gate[2*NN*CC];

__device__ __forceinline__ float sigmoidf_(float x){ return 1.f/(1.f+expf(-x)); }
__device__ __forceinline__ float siluf_(float x){ return x/(1.f+expf(-x)); }

// packed f32x2 FMA (SASS FFMA2) — only reachable via PTX
#define FMA2(d, a, b, c) \
    asm("fma.rn.f32x2 %0, %1, %2, %3;" : "=l"(d) : "l"(a), "l"(b), "l"(c))
#define UNPACK2(lo, hi, v) \
    asm("mov.b64 {%0, %1}, %2;" : "=f"(lo), "=f"(hi) : "l"(v))

// ---------------- kernel 1: convs + per-block stats + val/key store ----------------
// smem: xs[64][128] | w2a (conv_w dup, float2[64][64]) | w2b (val_w dup) | small
#define SM_XS   0
#define SM_W2A  8192
#define SM_W2B  16384
#define SM_KWS  24576
#define SM_VSC  24640
#define SM_VSH  24704
#define SM_KK   24768
#define SM1_FLOATS 24896   /* 99584 bytes */

extern __shared__ float sm1[];

__global__ __launch_bounds__(256) void k1(
    const float* __restrict__ rgb, const float* __restrict__ ir,
    const float* __restrict__ conv_w, const float* __restrict__ val_w,
    const float* __restrict__ key_w,
    const float* __restrict__ key_g, const float* __restrict__ key_b,
    const float* __restrict__ key_m, const float* __restrict__ key_v,
    const float* __restrict__ val_g, const float* __restrict__ val_b,
    const float* __restrict__ val_m, const float* __restrict__ val_v)
{
    float* xs  = sm1 + SM_XS;
    float* w2a = sm1 + SM_W2A;   // duplicated weights: w2a[(c*64+o)*2 + {0,1}] = conv_w[o][c]
    float* w2b = sm1 + SM_W2B;
    float* kws = sm1 + SM_KWS;
    float* vsc = sm1 + SM_VSC;
    float* vsh = sm1 + SM_VSH;
    float* kk  = sm1 + SM_KK;

    const int tid = threadIdx.x;
    const int s = blockIdx.z, n = blockIdx.y, blk = blockIdx.x;
    const int e0 = blk * P1;
    const float* x = (s == 0 ? rgb : ir) + (size_t)n * CC * HW;

    // load x tile [64 ch][128 pix] (float4, coalesced)
    #pragma unroll
    for (int i = 0; i < 8; i++) {
        int idx = tid + i * 256;          // 2048 float4 total
        int c = idx >> 5, p4 = idx & 31;
        float4 v = *reinterpret_cast<const float4*>(x + (size_t)c * HW + e0 + (p4 << 2));
        *reinterpret_cast<float4*>(xs + c * P1 + (p4 << 2)) = v;
    }
    // both weight tiles, transposed + duplicated: w2[c][o] = (w, w)
    for (int idx = tid; idx < 4096; idx += 256) {
        int o = idx >> 6, c = idx & 63;
        float wa = conv_w[idx], wb = val_w[idx];
        int d = (c * 64 + o) * 2;
        w2a[d] = wa; w2a[d + 1] = wa;
        w2b[d] = wb; w2b[d + 1] = wb;
    }
    if (tid < 64) {
        kws[tid] = key_w[tid];
        float sc = val_g[tid] * rsqrtf(val_v[tid] + EPS);
        vsc[tid] = sc; vsh[tid] = val_b[tid] - val_m[tid] * sc;
    }
    __syncthreads();

    const int og = tid >> 5, pg = tid & 31;   // warp = 8 out-channels, lane = 4 pixels
    const ulonglong2* xrow = reinterpret_cast<const ulonglong2*>(xs);   // [c*32 + pg]
    const ulonglong2* wta  = reinterpret_cast<const ulonglong2*>(w2a);  // [c*32 + og*4 + jj]
    const ulonglong2* wtb  = reinterpret_cast<const ulonglong2*>(w2b);

    // ---- phase A: xc conv (packed f32x2), reduce sum/max over pixels ----
    unsigned long long a01[8], a23[8];
    #pragma unroll
    for (int j = 0; j < 8; j++) { a01[j] = 0ull; a23[j] = 0ull; }
    #pragma unroll 8
    for (int c = 0; c < CC; c++) {
        ulonglong2 xv = xrow[c * 32 + pg];          // pix(0,1) | pix(2,3)
        const ulonglong2* wr = wta + c * 32 + (og << 2);
        #pragma unroll
        for (int jj = 0; jj < 4; jj++) {
            ulonglong2 wp = wr[jj];                  // (w_j,w_j) | (w_{j+1},w_{j+1})
            FMA2(a01[2*jj],   xv.x, wp.x, a01[2*jj]);
            FMA2(a23[2*jj],   xv.y, wp.x, a23[2*jj]);
            FMA2(a01[2*jj+1], xv.x, wp.y, a01[2*jj+1]);
            FMA2(a23[2*jj+1], xv.y, wp.y, a23[2*jj+1]);
        }
    }
    #pragma unroll
    for (int j = 0; j < 8; j++) {
        float p0, p1, p2, p3;
        UNPACK2(p0, p1, a01[j]);
        UNPACK2(p2, p3, a23[j]);
        float sv = (p0 + p1) + (p2 + p3);
        float mv = fmaxf(fmaxf(p0, p1), fmaxf(p2, p3));
        #pragma unroll
        for (int off = 16; off; off >>= 1) {
            sv += __shfl_down_sync(0xffffffffu, sv, off);
            mv = fmaxf(mv, __shfl_down_sync(0xffffffffu, mv, off));
        }
        if (pg == 0) {
            size_t b = ((size_t)(s * NN + n) * NB1 + blk) * CC + (og << 3) + j;
            g_psum[b] = sv; g_pmax[b] = mv;
        }
    }

    // ---- key conv (1 x C) for 128 pixels ----
    if (tid < P1) {
        float ka = 0.f;
        #pragma unroll 8
        for (int c = 0; c < CC; c++) ka = fmaf(kws[c], xs[c * P1 + tid], ka);
        float ks = key_g[0] * rsqrtf(key_v[0] + EPS);
        float kb = key_b[0] - key_m[0] * ks;
        float t = ka * ks + kb;
        float kv = siluf_(t);
        kk[tid] = kv;
        g_k[(size_t)(s * NN + n) * HW + e0 + tid] = kv;
    }
    __syncthreads();

    if (tid < 32) {
        float m = fmaxf(fmaxf(kk[tid], kk[tid + 32]), fmaxf(kk[tid + 64], kk[tid + 96]));
        #pragma unroll
        for (int off = 16; off; off >>= 1) m = fmaxf(m, __shfl_xor_sync(0xffffffffu, m, off));
        float z = expf(kk[tid] - m) + expf(kk[tid + 32] - m) +
                  expf(kk[tid + 64] - m) + expf(kk[tid + 96] - m);
        #pragma unroll
        for (int off = 16; off; off >>= 1) z += __shfl_xor_sync(0xffffffffu, z, off);
        if (tid == 0) { int b = (s * NN + n) * NB1 + blk; g_pkm[b] = m; g_pkz[b] = z; }
    }

    // ---- phase B: val conv (weights already resident) ----
    #pragma unroll
    for (int j = 0; j < 8; j++) { a01[j] = 0ull; a23[j] = 0ull; }
    #pragma unroll 8
    for (int c = 0; c < CC; c++) {
        ulonglong2 xv = xrow[c * 32 + pg];
        const ulonglong2* wr = wtb + c * 32 + (og << 2);
        #pragma unroll
        for (int jj = 0; jj < 4; jj++) {
            ulonglong2 wp = wr[jj];
            FMA2(a01[2*jj],   xv.x, wp.x, a01[2*jj]);
            FMA2(a23[2*jj],   xv.y, wp.x, a23[2*jj]);
            FMA2(a01[2*jj+1], xv.x, wp.y, a01[2*jj+1]);
            FMA2(a23[2*jj+1], xv.y, wp.y, a23[2*jj+1]);
        }
    }
    float* vout = g_val + ((size_t)(s * NN + n) * HW + e0) * CC;
    float ap[4][8];
    #pragma unroll
    for (int j = 0; j < 8; j++) {
        UNPACK2(ap[0][j], ap[1][j], a01[j]);
        UNPACK2(ap[2][j], ap[3][j], a23[j]);
    }
    #pragma unroll
    for (int p = 0; p < 4; p++) {
        float vv[8];
        #pragma unroll
        for (int j = 0; j < 8; j++) {
            int o = (og << 3) + j;
            float t = fmaf(ap[p][j], vsc[o], vsh[o]);
            vv[j] = siluf_(t);
        }
        size_t base = (size_t)((pg << 2) + p) * CC + (og << 3);
        *reinterpret_cast<float4*>(vout + base)     = make_float4(vv[0], vv[1], vv[2], vv[3]);
        *reinterpret_cast<float4*>(vout + base + 4) = make_float4(vv[4], vv[5], vv[6], vv[7]);
    }
}

// ---------------- block-of-64 reductions ----------------
__device__ __forceinline__ float blk64_max(float v, float* red, int c) {
    red[c] = v; __syncthreads();
    for (int st = 32; st >= 1; st >>= 1) { if (c < st) red[c] = fmaxf(red[c], red[c + st]); __syncthreads(); }
    float r = red[0]; __syncthreads(); return r;
}
__device__ __forceinline__ float blk64_sum(float v, float* red, int c) {
    red[c] = v; __syncthreads();
    for (int st = 32; st >= 1; st >>= 1) { if (c < st) red[c] += red[c + st]; __syncthreads(); }
    float r = red[0]; __syncthreads(); return r;
}

// ---------------- kernel 2: finalize stats (avg/mx softmax, key M/Z) ----------------
__global__ __launch_bounds__(64) void k2(const float* __restrict__ conv_b)
{
    const int n = blockIdx.x, s = blockIdx.y, c = threadIdx.x;
    __shared__ float red[64];
    const size_t base = (size_t)(s * NN + n) * NB1;

    float sv = 0.f, mv = -3.0e38f;
    for (int b = 0; b < NB1; b++) {
        sv += g_psum[(base + b) * CC + c];
        mv = fmaxf(mv, g_pmax[(base + b) * CC + c]);
    }
    float mean = sv * (1.f / HW) + conv_b[c];
    float mx   = mv + conv_b[c];

    float am = blk64_max(mean, red, c);
    float ea = expf(mean - am);
    float za = blk64_sum(ea, red, c);
    g_avg[(s * NN + n) * CC + c] = ea / za;

    float mm = blk64_max(mx, red, c);
    float em = expf(mx - mm);
    float zm = blk64_sum(em, red, c);
    g_mx[(s * NN + n) * CC + c] = em / zm;

    float km = -3.0e38f;
    for (int b = c; b < NB1; b += 64) km = fmaxf(km, g_pkm[base + b]);
    float M = blk64_max(km, red, c);
    float z = 0.f;
    for (int b = c; b < NB1; b += 64) z += g_pkz[base + b] * expf(g_pkm[base + b] - M);
    float Z = blk64_sum(z, red, c);
    if (c == 0) { g_kM[s * NN + n] = M; g_kZ[s * NN + n] = Z; }
}

// ---------------- kernel 2.5: fea partials = sum_e val[1-s]*softkey[s] ----------------
__global__ __launch_bounds__(256) void k25()
{
    const int s = blockIdx.z, n = blockIdx.y, ch = blockIdx.x;
    const int tid = threadIdx.x;
    const int e0 = ch * CH25;
    __shared__ float wk[CH25];
    __shared__ float pr[256];

    const float M = g_kM[s * NN + n];
    const float invZ = 1.f / g_kZ[s * NN + n];
    const float* kp = g_k + (size_t)(s * NN + n) * HW + e0;
    for (int i = tid; i < CH25; i += 256) wk[i] = expf(kp[i] - M) * invZ;
    __syncthreads();

    const int c = tid & 63, r = tid >> 6;
    const float* vp = g_val + ((size_t)((1 - s) * NN + n) * HW + e0) * CC;
    float acc = 0.f;
    for (int i = r; i < CH25; i += 4) acc = fmaf(vp[(size_t)i * CC + c], wk[i], acc);
    pr[tid] = acc; __syncthreads();
    if (r == 0)
        g_feap[((size_t)(s * NN + n) * NB25 + ch) * CC + c] =
            pr[c] + pr[64 + c] + pr[128 + c] + pr[192 + c];
}

// ---------------- kernel 2.75: gate = sigmoid(LN(fea @ convb^T)) ----------------
__global__ __launch_bounds__(64) void k27(
    const float* __restrict__ convb_w, const float* __restrict__ ln_g, const float* __restrict__ ln_b)
{
    const int n = blockIdx.x, s = blockIdx.y, c = threadIdx.x;
    __shared__ float feas[64];
    __shared__ float red[64];
    const size_t base = (size_t)(s * NN + n) * NB25 * CC;
    float f = 0.f;
    for (int b = 0; b < NB25; b++) f += g_feap[base + (size_t)b * CC + c];
    feas[c] = f; __syncthreads();

    float g = 0.f;
    #pragma unroll 8
    for (int j = 0; j < CC; j++) g = fmaf(convb_w[c * CC + j], feas[j], g);

    float mu  = blk64_sum(g, red, c) * (1.f / CC);
    float d   = g - mu;
    float var = blk64_sum(d * d, red, c) * (1.f / CC);
    float zz  = d * rsqrtf(var + EPS) * ln_g[c] + ln_b[c];
    g_gate[(s * NN + n) * CC + c] = sigmoidf_(zz);
}

// ---------------- kernel 3: output = gate * half + me ----------------
__global__ __launch_bounds__(256) void k3(
    const float* __restrict__ rgb, const float* __restrict__ ir, float* __restrict__ out,
    const float* __restrict__ half_w,
    const float* __restrict__ half_g, const float* __restrict__ half_b,
    const float* __restrict__ half_m, const float* __restrict__ half_v)
{
    const int s = blockIdx.z, n = blockIdx.y;
    const int e0 = blockIdx.x * P3;
    const int tid = threadIdx.x;
    __shared__ __align__(16) float avs[64];
    __shared__ __align__(16) float mxs[64];
    __shared__ __align__(16) float gts[64];
    if (tid < 64) {
        int i = (s * NN + n) * CC + tid;
        avs[tid] = g_avg[i]; mxs[tid] = g_mx[i]; gts[tid] = g_gate[i];
    }
    __syncthreads();

    const float* vp = g_val + ((size_t)((1 - s) * NN + n) * HW + e0 + tid) * CC;
    float aA = 0.f, aM = 0.f;
    #pragma unroll
    for (int c4 = 0; c4 < 16; c4++) {
        float4 v = reinterpret_cast<const float4*>(vp)[c4];
        float4 a = reinterpret_cast<const float4*>(avs)[c4];
        float4 m = reinterpret_cast<const float4*>(mxs)[c4];
        aA += v.x * a.x + v.y * a.y + v.z * a.z + v.w * a.w;
        aM += v.x * m.x + v.y * m.y + v.z * m.z + v.w * m.w;
    }
    float hs = half_g[0] * rsqrtf(half_v[0] + EPS);
    float hb = half_b[0] - half_m[0] * hs;
    float pre = half_w[0] * aA + half_w[1] * aM;
    float hlf = siluf_(pre * hs + hb);

    const float* xme = (s == 0 ? rgb : ir) + (size_t)n * CC * HW;
    float* op = out + (size_t)(s * NN + n) * CC * HW;
    #pragma unroll 4
    for (int c = 0; c < CC; c++) {
        size_t idx = (size_t)c * HW + e0 + tid;
        op[idx] = fmaf(gts[c], hlf, xme[idx]);
    }
}

// ---------------- launch ----------------
extern "C" void kernel_launch(void* const* d_in, const int* in_sizes, int n_in,
                              void* d_out, int out_size)
{
    const float* rgb     = (const float*)d_in[0];
    const float* ir      = (const float*)d_in[1];
    const float* conv_w  = (const float*)d_in[2];
    const float* conv_b  = (const float*)d_in[3];
    const float* key_w   = (const float*)d_in[4];
    const float* key_g   = (const float*)d_in[5];
    const float* key_b   = (const float*)d_in[6];
    const float* key_m   = (const float*)d_in[7];
    const float* key_v   = (const float*)d_in[8];
    const float* val_w   = (const float*)d_in[9];
    const float* val_g   = (const float*)d_in[10];
    const float* val_b   = (const float*)d_in[11];
    const float* val_m   = (const float*)d_in[12];
    const float* val_v   = (const float*)d_in[13];
    const float* convb_w = (const float*)d_in[14];
    const float* half_w  = (const float*)d_in[15];
    const float* half_g  = (const float*)d_in[16];
    const float* half_b  = (const float*)d_in[17];
    const float* half_m  = (const float*)d_in[18];
    const float* half_v  = (const float*)d_in[19];
    const float* ln_g    = (const float*)d_in[20];
    const float* ln_b    = (const float*)d_in[21];
    float* out = (float*)d_out;

    const size_t smem1 = SM1_FLOATS * sizeof(float);   // 99584 B
    cudaFuncSetAttribute(k1, cudaFuncAttributeMaxDynamicSharedMemorySize, (int)smem1);

    k1<<<dim3(NB1, NN, 2), 256, smem1>>>(rgb, ir, conv_w, val_w, key_w,
                                         key_g, key_b, key_m, key_v,
                                         val_g, val_b, val_m, val_v);
    k2<<<dim3(NN, 2), 64>>>(conv_b);
    k25<<<dim3(NB25, NN, 2), 256>>>();
    k27<<<dim3(NN, 2), 64>>>(convb_w, ln_g, ln_b);
    k3<<<dim3(NB3, NN, 2), 256>>>(rgb, ir, out, half_w, half_g, half_b, half_m, half_v);
}

// round 4
// speedup vs baseline: 1.7130x; 1.7130x over previous
#include <cuda_runtime.h>
#include <math.h>

#define EPS 1e-5f
#define CC 64
#define NN 8
#define HW 65536
#define P1 256
#define NB1 (HW/P1)      /* 256 blocks for k1/k2 partials */
#define CH25 1024
#define NB25 (HW/CH25)   /* 64 */
#define P3 256
#define NB3 (HW/P3)      /* 256 */

// ---------------- scratch (__device__ globals; no allocation) ----------------
__device__ float g_val[(size_t)2*NN*HW*CC];   // 256 MiB, layout [side][n][pix][c]
__device__ float g_k[2*NN*HW];                // silu'd key values
__device__ float g_psum[2*NN*NB1*CC];
__device__ float g_pmax[2*NN*NB1*CC];
__device__ float g_pkm[2*NN*NB1];
__device__ float g_pkz[2*NN*NB1];
__device__ float g_avg[2*NN*CC];
__device__ float g_mx[2*NN*CC];
__device__ float g_kM[2*NN];
__device__ float g_kZ[2*NN];
__device__ float g_feap[2*NN*NB25*CC];
__device__ float g_gate[2*NN*CC];

__device__ __forceinline__ float sigmoidf_(float x){ return 1.f/(1.f+expf(-x)); }
__device__ __forceinline__ float siluf_(float x){ return x/(1.f+expf(-x)); }

__device__ __forceinline__ unsigned tf32_(float f){
    unsigned u; asm("cvt.rna.tf32.f32 %0, %1;" : "=r"(u) : "f"(f)); return u;
}

// m16n8k8 tf32 mma, f32 accumulate
#define MMA_TF32(d, a, b) \
    asm volatile("mma.sync.aligned.m16n8k8.row.col.f32.tf32.tf32.f32 " \
        "{%0,%1,%2,%3}, {%4,%5,%6,%7}, {%8,%9}, {%0,%1,%2,%3};" \
        : "+f"((d)[0]), "+f"((d)[1]), "+f"((d)[2]), "+f"((d)[3]) \
        : "r"((a)[0]), "r"((a)[1]), "r"((a)[2]), "r"((a)[3]), \
          "r"((b)[0]), "r"((b)[1]))

// ---------------- kernel 1 smem layout (floats) ----------------
#define XSTR 264          /* x tile row stride (64 rows) — banks (8k+pix)%32 distinct */
#define WSTR 68           /* weight tile row stride — banks (4g+t)%32 distinct */
#define VSTR 68           /* staged val row stride */
#define SM_X    0         /* x tile (uint tf32) 64*264=16896; reused as vals 256*68=17408 */
#define SM_WA   17408     /* conv_w tf32, 64*68=4352 */
#define SM_WB   21760     /* val_w tf32 */
#define SM_KWS  26112
#define SM_VSC  26176
#define SM_VSH  26240
#define SM_KK   26304     /* 256 key values */
#define SM_PS   26560     /* per-warp channel sums [8][64] */
#define SM_PM   27072     /* per-warp channel maxes [8][64] */
#define SM1_FLOATS 27584  /* 110336 bytes */

extern __shared__ float sm1[];

__device__ __forceinline__ void gemm_tile(const unsigned* __restrict__ xs,
                                          const unsigned* __restrict__ wp,
                                          float acc[16][4], int pixbase, int g, int t)
{
    #pragma unroll
    for (int ks = 0; ks < 8; ks++) {
        unsigned bfr[4][2];
        #pragma unroll
        for (int nt = 0; nt < 4; nt++) {
            int pcol = pixbase + nt * 8 + g;
            bfr[nt][0] = xs[(ks * 8 + t) * XSTR + pcol];
            bfr[nt][1] = xs[(ks * 8 + t + 4) * XSTR + pcol];
        }
        unsigned afr[4][4];
        #pragma unroll
        for (int mt = 0; mt < 4; mt++) {
            int row = mt * 16 + g;
            afr[mt][0] = wp[row * WSTR + ks * 8 + t];
            afr[mt][1] = wp[(row + 8) * WSTR + ks * 8 + t];
            afr[mt][2] = wp[row * WSTR + ks * 8 + t + 4];
            afr[mt][3] = wp[(row + 8) * WSTR + ks * 8 + t + 4];
        }
        #pragma unroll
        for (int mt = 0; mt < 4; mt++)
            #pragma unroll
            for (int nt = 0; nt < 4; nt++)
                MMA_TF32(acc[mt * 4 + nt], afr[mt], bfr[nt]);
    }
}

__global__ __launch_bounds__(256) void k1(
    const float* __restrict__ rgb, const float* __restrict__ ir,
    const float* __restrict__ conv_w, const float* __restrict__ val_w,
    const float* __restrict__ key_w,
    const float* __restrict__ key_g, const float* __restrict__ key_b,
    const float* __restrict__ key_m, const float* __restrict__ key_v,
    const float* __restrict__ val_g, const float* __restrict__ val_b,
    const float* __restrict__ val_m, const float* __restrict__ val_v)
{
    unsigned* xs = reinterpret_cast<unsigned*>(sm1 + SM_X);
    unsigned* wa = reinterpret_cast<unsigned*>(sm1 + SM_WA);
    unsigned* wb = reinterpret_cast<unsigned*>(sm1 + SM_WB);
    float* kws = sm1 + SM_KWS;
    float* vsc = sm1 + SM_VSC;
    float* vsh = sm1 + SM_VSH;
    float* kk  = sm1 + SM_KK;
    float* ps  = sm1 + SM_PS;
    float* pm  = sm1 + SM_PM;

    const int tid = threadIdx.x;
    const int wid = tid >> 5, lane = tid & 31;
    const int g = lane >> 2, t = lane & 3;
    const int s = blockIdx.z, n = blockIdx.y, blk = blockIdx.x;
    const int e0 = blk * P1;
    const float* x = (s == 0 ? rgb : ir) + (size_t)n * CC * HW;

    // ---- fill x tile (cvt to tf32), coalesced float4 ----
    #pragma unroll
    for (int i = 0; i < 16; i++) {
        int idx = tid + i * 256;            // 4096 float4
        int r = idx >> 6, c4 = idx & 63;
        float4 v = *reinterpret_cast<const float4*>(x + (size_t)r * HW + e0 + (c4 << 2));
        uint4 u = make_uint4(tf32_(v.x), tf32_(v.y), tf32_(v.z), tf32_(v.w));
        *reinterpret_cast<uint4*>(xs + r * XSTR + (c4 << 2)) = u;
    }
    for (int idx = tid; idx < 4096; idx += 256) {
        int o = idx >> 6, c = idx & 63;
        wa[o * WSTR + c] = tf32_(conv_w[idx]);
        wb[o * WSTR + c] = tf32_(val_w[idx]);
    }
    if (tid < 64) {
        kws[tid] = key_w[tid];
        float sc = val_g[tid] * rsqrtf(val_v[tid] + EPS);
        vsc[tid] = sc; vsh[tid] = val_b[tid] - val_m[tid] * sc;
    }
    __syncthreads();

    const int pixbase = wid * 32;
    float acc[16][4];

    // ================= phase A: xc conv =================
    #pragma unroll
    for (int i = 0; i < 16; i++) { acc[i][0]=0.f; acc[i][1]=0.f; acc[i][2]=0.f; acc[i][3]=0.f; }
    gemm_tile(xs, wa, acc, pixbase, g, t);

    // epilogue A: per-warp channel sum/max over 32 pixels
    #pragma unroll
    for (int mt = 0; mt < 4; mt++) {
        float slo = 0.f, shi = 0.f, mlo = -3.0e38f, mhi = -3.0e38f;
        #pragma unroll
        for (int nt = 0; nt < 4; nt++) {
            float c0 = acc[mt*4+nt][0], c1 = acc[mt*4+nt][1];
            float c2 = acc[mt*4+nt][2], c3 = acc[mt*4+nt][3];
            slo += c0 + c1; shi += c2 + c3;
            mlo = fmaxf(mlo, fmaxf(c0, c1));
            mhi = fmaxf(mhi, fmaxf(c2, c3));
        }
        #pragma unroll
        for (int off = 1; off < 4; off <<= 1) {
            slo += __shfl_xor_sync(0xffffffffu, slo, off);
            shi += __shfl_xor_sync(0xffffffffu, shi, off);
            mlo = fmaxf(mlo, __shfl_xor_sync(0xffffffffu, mlo, off));
            mhi = fmaxf(mhi, __shfl_xor_sync(0xffffffffu, mhi, off));
        }
        if (t == 0) {
            ps[wid * 64 + mt * 16 + g]     = slo;
            ps[wid * 64 + mt * 16 + g + 8] = shi;
            pm[wid * 64 + mt * 16 + g]     = mlo;
            pm[wid * 64 + mt * 16 + g + 8] = mhi;
        }
    }

    // ---- key conv: one pixel per thread (reads tf32 bits as float) ----
    {
        const float* xf = reinterpret_cast<const float*>(xs);
        float ka = 0.f;
        #pragma unroll 8
        for (int c = 0; c < CC; c++) ka = fmaf(kws[c], xf[c * XSTR + tid], ka);
        float kscale = key_g[0] * rsqrtf(key_v[0] + EPS);
        float kbias = key_b[0] - key_m[0] * kscale;
        float kv = siluf_(ka * kscale + kbias);
        kk[tid] = kv;
        g_k[(size_t)(s * NN + n) * HW + e0 + tid] = kv;
    }
    __syncthreads();

    // block-level finals: channels by warps 0-1, key softmax by warp 2
    if (tid < 64) {
        float sv = 0.f, mv = -3.0e38f;
        #pragma unroll
        for (int w = 0; w < 8; w++) {
            sv += ps[w * 64 + tid];
            mv = fmaxf(mv, pm[w * 64 + tid]);
        }
        size_t b = ((size_t)(s * NN + n) * NB1 + blk) * CC + tid;
        g_psum[b] = sv; g_pmax[b] = mv;
    }
    if (wid == 2) {
        float m = kk[lane];
        #pragma unroll
        for (int i = 1; i < 8; i++) m = fmaxf(m, kk[lane + 32 * i]);
        #pragma unroll
        for (int off = 16; off; off >>= 1) m = fmaxf(m, __shfl_xor_sync(0xffffffffu, m, off));
        float z = 0.f;
        #pragma unroll
        for (int i = 0; i < 8; i++) z += expf(kk[lane + 32 * i] - m);
        #pragma unroll
        for (int off = 16; off; off >>= 1) z += __shfl_xor_sync(0xffffffffu, z, off);
        if (lane == 0) { int b = (s * NN + n) * NB1 + blk; g_pkm[b] = m; g_pkz[b] = z; }
    }

    // ================= phase B: val conv =================
    #pragma unroll
    for (int i = 0; i < 16; i++) { acc[i][0]=0.f; acc[i][1]=0.f; acc[i][2]=0.f; acc[i][3]=0.f; }
    gemm_tile(xs, wb, acc, pixbase, g, t);

    __syncthreads();   // all warps done reading xs — safe to overwrite with vals
    float* vals = sm1 + SM_X;   // [256 pix][VSTR]
    #pragma unroll
    for (int mt = 0; mt < 4; mt++) {
        int o  = mt * 16 + g;
        int o2 = o + 8;
        float sc = vsc[o],  sh = vsh[o];
        float sc2 = vsc[o2], sh2 = vsh[o2];
        #pragma unroll
        for (int nt = 0; nt < 4; nt++) {
            int p0 = pixbase + nt * 8 + 2 * t;
            vals[p0 * VSTR + o]        = siluf_(fmaf(acc[mt*4+nt][0], sc, sh));
            vals[(p0 + 1) * VSTR + o]  = siluf_(fmaf(acc[mt*4+nt][1], sc, sh));
            vals[p0 * VSTR + o2]       = siluf_(fmaf(acc[mt*4+nt][2], sc2, sh2));
            vals[(p0 + 1) * VSTR + o2] = siluf_(fmaf(acc[mt*4+nt][3], sc2, sh2));
        }
    }
    __syncthreads();
    // coalesced store: one pixel per thread, 16 float4
    {
        const float4* vrow = reinterpret_cast<const float4*>(vals + tid * VSTR);
        float4* vo = reinterpret_cast<float4*>(g_val + ((size_t)(s * NN + n) * HW + e0 + tid) * CC);
        #pragma unroll
        for (int i = 0; i < 16; i++) vo[i] = vrow[i];
    }
}

// ---------------- block-of-64 reductions ----------------
__device__ __forceinline__ float blk64_max(float v, float* red, int c) {
    red[c] = v; __syncthreads();
    for (int st = 32; st >= 1; st >>= 1) { if (c < st) red[c] = fmaxf(red[c], red[c + st]); __syncthreads(); }
    float r = red[0]; __syncthreads(); return r;
}
__device__ __forceinline__ float blk64_sum(float v, float* red, int c) {
    red[c] = v; __syncthreads();
    for (int st = 32; st >= 1; st >>= 1) { if (c < st) red[c] += red[c + st]; __syncthreads(); }
    float r = red[0]; __syncthreads(); return r;
}

// ---------------- kernel 2: finalize stats (avg/mx softmax, key M/Z) ----------------
__global__ __launch_bounds__(64) void k2(const float* __restrict__ conv_b)
{
    const int n = blockIdx.x, s = blockIdx.y, c = threadIdx.x;
    __shared__ float red[64];
    const size_t base = (size_t)(s * NN + n) * NB1;

    float sv = 0.f, mv = -3.0e38f;
    for (int b = 0; b < NB1; b++) {
        sv += g_psum[(base + b) * CC + c];
        mv = fmaxf(mv, g_pmax[(base + b) * CC + c]);
    }
    float mean = sv * (1.f / HW) + conv_b[c];
    float mx   = mv + conv_b[c];

    float am = blk64_max(mean, red, c);
    float ea = expf(mean - am);
    float za = blk64_sum(ea, red, c);
    g_avg[(s * NN + n) * CC + c] = ea / za;

    float mm = blk64_max(mx, red, c);
    float em = expf(mx - mm);
    float zm = blk64_sum(em, red, c);
    g_mx[(s * NN + n) * CC + c] = em / zm;

    float km = -3.0e38f;
    for (int b = c; b < NB1; b += 64) km = fmaxf(km, g_pkm[base + b]);
    float M = blk64_max(km, red, c);
    float z = 0.f;
    for (int b = c; b < NB1; b += 64) z += g_pkz[base + b] * expf(g_pkm[base + b] - M);
    float Z = blk64_sum(z, red, c);
    if (c == 0) { g_kM[s * NN + n] = M; g_kZ[s * NN + n] = Z; }
}

// ---------------- kernel 2.5: fea partials = sum_e val[1-s]*softkey[s] ----------------
__global__ __launch_bounds__(256) void k25()
{
    const int s = blockIdx.z, n = blockIdx.y, ch = blockIdx.x;
    const int tid = threadIdx.x;
    const int e0 = ch * CH25;
    __shared__ float wk[CH25];
    __shared__ float pr[256];

    const float M = g_kM[s * NN + n];
    const float invZ = 1.f / g_kZ[s * NN + n];
    const float* kp = g_k + (size_t)(s * NN + n) * HW + e0;
    for (int i = tid; i < CH25; i += 256) wk[i] = expf(kp[i] - M) * invZ;
    __syncthreads();

    const int c = tid & 63, r = tid >> 6;
    const float* vp = g_val + ((size_t)((1 - s) * NN + n) * HW + e0) * CC;
    float acc = 0.f;
    for (int i = r; i < CH25; i += 4) acc = fmaf(vp[(size_t)i * CC + c], wk[i], acc);
    pr[tid] = acc; __syncthreads();
    if (r == 0)
        g_feap[((size_t)(s * NN + n) * NB25 + ch) * CC + c] =
            pr[c] + pr[64 + c] + pr[128 + c] + pr[192 + c];
}

// ---------------- kernel 2.75: gate = sigmoid(LN(fea @ convb^T)) ----------------
__global__ __launch_bounds__(64) void k27(
    const float* __restrict__ convb_w, const float* __restrict__ ln_g, const float* __restrict__ ln_b)
{
    const int n = blockIdx.x, s = blockIdx.y, c = threadIdx.x;
    __shared__ float feas[64];
    __shared__ float red[64];
    const size_t base = (size_t)(s * NN + n) * NB25 * CC;
    float f = 0.f;
    for (int b = 0; b < NB25; b++) f += g_feap[base + (size_t)b * CC + c];
    feas[c] = f; __syncthreads();

    float g = 0.f;
    #pragma unroll 8
    for (int j = 0; j < CC; j++) g = fmaf(convb_w[c * CC + j], feas[j], g);

    float mu  = blk64_sum(g, red, c) * (1.f / CC);
    float d   = g - mu;
    float var = blk64_sum(d * d, red, c) * (1.f / CC);
    float zz  = d * rsqrtf(var + EPS) * ln_g[c] + ln_b[c];
    g_gate[(s * NN + n) * CC + c] = sigmoidf_(zz);
}

// ---------------- kernel 3: output = gate * half + me ----------------
__global__ __launch_bounds__(256) void k3(
    const float* __restrict__ rgb, const float* __restrict__ ir, float* __restrict__ out,
    const float* __restrict__ half_w,
    const float* __restrict__ half_g, const float* __restrict__ half_b,
    const float* __restrict__ half_m, const float* __restrict__ half_v)
{
    const int s = blockIdx.z, n = blockIdx.y;
    const int e0 = blockIdx.x * P3;
    const int tid = threadIdx.x;
    __shared__ __align__(16) float avs[64];
    __shared__ __align__(16) float mxs[64];
    __shared__ __align__(16) float gts[64];
    if (tid < 64) {
        int i = (s * NN + n) * CC + tid;
        avs[tid] = g_avg[i]; mxs[tid] = g_mx[i]; gts[tid] = g_gate[i];
    }
    __syncthreads();

    const float* vp = g_val + ((size_t)((1 - s) * NN + n) * HW + e0 + tid) * CC;
    float aA = 0.f, aM = 0.f;
    #pragma unroll
    for (int c4 = 0; c4 < 16; c4++) {
        float4 v = reinterpret_cast<const float4*>(vp)[c4];
        float4 a = reinterpret_cast<const float4*>(avs)[c4];
        float4 m = reinterpret_cast<const float4*>(mxs)[c4];
        aA += v.x * a.x + v.y * a.y + v.z * a.z + v.w * a.w;
        aM += v.x * m.x + v.y * m.y + v.z * m.z + v.w * m.w;
    }
    float hs = half_g[0] * rsqrtf(half_v[0] + EPS);
    float hb = half_b[0] - half_m[0] * hs;
    float pre = half_w[0] * aA + half_w[1] * aM;
    float hlf = siluf_(pre * hs + hb);

    const float* xme = (s == 0 ? rgb : ir) + (size_t)n * CC * HW;
    float* op = out + (size_t)(s * NN + n) * CC * HW;
    #pragma unroll 4
    for (int c = 0; c < CC; c++) {
        size_t idx = (size_t)c * HW + e0 + tid;
        op[idx] = fmaf(gts[c], hlf, xme[idx]);
    }
}

// ---------------- launch ----------------
extern "C" void kernel_launch(void* const* d_in, const int* in_sizes, int n_in,
                              void* d_out, int out_size)
{
    const float* rgb     = (const float*)d_in[0];
    const float* ir      = (const float*)d_in[1];
    const float* conv_w  = (const float*)d_in[2];
    const float* conv_b  = (const float*)d_in[3];
    const float* key_w   = (const float*)d_in[4];
    const float* key_g   = (const float*)d_in[5];
    const float* key_b   = (const float*)d_in[6];
    const float* key_m   = (const float*)d_in[7];
    const float* key_v   = (const float*)d_in[8];
    const float* val_w   = (const float*)d_in[9];
    const float* val_g   = (const float*)d_in[10];
    const float* val_b   = (const float*)d_in[11];
    const float* val_m   = (const float*)d_in[12];
    const float* val_v   = (const float*)d_in[13];
    const float* convb_w = (const float*)d_in[14];
    const float* half_w  = (const float*)d_in[15];
    const float* half_g  = (const float*)d_in[16];
    const float* half_b  = (const float*)d_in[17];
    const float* half_m  = (const float*)d_in[18];
    const float* half_v  = (const float*)d_in[19];
    const float* ln_g    = (const float*)d_in[20];
    const float* ln_b    = (const float*)d_in[21];
    float* out = (float*)d_out;

    const size_t smem1 = SM1_FLOATS * sizeof(float);   // 110336 B
    cudaFuncSetAttribute(k1, cudaFuncAttributeMaxDynamicSharedMemorySize, (int)smem1);

    k1<<<dim3(NB1, NN, 2), 256, smem1>>>(rgb, ir, conv_w, val_w, key_w,
                                         key_g, key_b, key_m, key_v,
                                         val_g, val_b, val_m, val_v);
    k2<<<dim3(NN, 2), 64>>>(conv_b);
    k25<<<dim3(NB25, NN, 2), 256>>>();
    k27<<<dim3(NN, 2), 64>>>(convb_w, ln_g, ln_b);
    k3<<<dim3(NB3, NN, 2), 256>>>(rgb, ir, out, half_w, half_g, half_b, half_m, half_v);
}

// round 5
// speedup vs baseline: 2.2888x; 1.3361x over previous
#include <cuda_runtime.h>
#include <cuda_bf16.h>
#include <math.h>

#define EPS 1e-5f
#define CC 64
#define NN 8
#define HW 65536
#define P1 256
#define NB1 (HW/P1)      /* 256 blocks for k1/k2 partials */
#define CH25 1024
#define NB25 (HW/CH25)   /* 64 */
#define P3 256
#define NB3 (HW/P3)      /* 256 */

// ---------------- scratch (__device__ globals; no allocation) ----------------
__device__ __nv_bfloat16 g_val[(size_t)2*NN*HW*CC];   // 134 MiB, [side][n][pix][c]
__device__ float g_k[2*NN*HW];                // silu'd key values
__device__ float g_psum[2*NN*NB1*CC];
__device__ float g_pmax[2*NN*NB1*CC];
__device__ float g_pkm[2*NN*NB1];
__device__ float g_pkz[2*NN*NB1];
__device__ float g_avg[2*NN*CC];
__device__ float g_mx[2*NN*CC];
__device__ float g_kM[2*NN];
__device__ float g_kZ[2*NN];
__device__ float g_feap[2*NN*NB25*CC];
__device__ float g_gate[2*NN*CC];

__device__ __forceinline__ float fexp_(float x){ return __expf(x); }
__device__ __forceinline__ float sigmoidf_(float x){ return __fdividef(1.f, 1.f + __expf(-x)); }
__device__ __forceinline__ float siluf_(float x){ return __fdividef(x, 1.f + __expf(-x)); }

__device__ __forceinline__ unsigned tf32_(float f){
    unsigned u; asm("cvt.rna.tf32.f32 %0, %1;" : "=r"(u) : "f"(f)); return u;
}

// m16n8k8 tf32 mma, f32 accumulate
#define MMA_TF32(d, a, b) \
    asm volatile("mma.sync.aligned.m16n8k8.row.col.f32.tf32.tf32.f32 " \
        "{%0,%1,%2,%3}, {%4,%5,%6,%7}, {%8,%9}, {%0,%1,%2,%3};" \
        : "+f"((d)[0]), "+f"((d)[1]), "+f"((d)[2]), "+f"((d)[3]) \
        : "r"((a)[0]), "r"((a)[1]), "r"((a)[2]), "r"((a)[3]), \
          "r"((b)[0]), "r"((b)[1]))

// ---------------- kernel 1 smem layout (floats) ----------------
#define XSTR 264          /* x tile row stride (64 rows) */
#define WSTR 68           /* weight tile row stride */
#define VSTR 68           /* staged val row stride */
#define SM_X    0         /* x tile (uint tf32) 64*264=16896; reused as vals 256*68=17408 */
#define SM_WA   17408     /* conv_w tf32, 64*68=4352 */
#define SM_WB   21760     /* val_w tf32 */
#define SM_KWS  26112
#define SM_VSC  26176
#define SM_VSH  26240
#define SM_KK   26304     /* 256 key values */
#define SM_PS   26560     /* per-warp channel sums [8][64] */
#define SM_PM   27072     /* per-warp channel maxes [8][64] */
#define SM1_FLOATS 27584  /* 110336 bytes */

extern __shared__ float sm1[];

__device__ __forceinline__ void gemm_tile(const unsigned* __restrict__ xs,
                                          const unsigned* __restrict__ wp,
                                          float acc[16][4], int pixbase, int g, int t)
{
    #pragma unroll
    for (int ks = 0; ks < 8; ks++) {
        unsigned bfr[4][2];
        #pragma unroll
        for (int nt = 0; nt < 4; nt++) {
            int pcol = pixbase + nt * 8 + g;
            bfr[nt][0] = xs[(ks * 8 + t) * XSTR + pcol];
            bfr[nt][1] = xs[(ks * 8 + t + 4) * XSTR + pcol];
        }
        unsigned afr[4][4];
        #pragma unroll
        for (int mt = 0; mt < 4; mt++) {
            int row = mt * 16 + g;
            afr[mt][0] = wp[row * WSTR + ks * 8 + t];
            afr[mt][1] = wp[(row + 8) * WSTR + ks * 8 + t];
            afr[mt][2] = wp[row * WSTR + ks * 8 + t + 4];
            afr[mt][3] = wp[(row + 8) * WSTR + ks * 8 + t + 4];
        }
        #pragma unroll
        for (int mt = 0; mt < 4; mt++)
            #pragma unroll
            for (int nt = 0; nt < 4; nt++)
                MMA_TF32(acc[mt * 4 + nt], afr[mt], bfr[nt]);
    }
}

__global__ __launch_bounds__(256) void k1(
    const float* __restrict__ rgb, const float* __restrict__ ir,
    const float* __restrict__ conv_w, const float* __restrict__ val_w,
    const float* __restrict__ key_w,
    const float* __restrict__ key_g, const float* __restrict__ key_b,
    const float* __restrict__ key_m, const float* __restrict__ key_v,
    const float* __restrict__ val_g, const float* __restrict__ val_b,
    const float* __restrict__ val_m, const float* __restrict__ val_v)
{
    unsigned* xs = reinterpret_cast<unsigned*>(sm1 + SM_X);
    unsigned* wa = reinterpret_cast<unsigned*>(sm1 + SM_WA);
    unsigned* wb = reinterpret_cast<unsigned*>(sm1 + SM_WB);
    float* kws = sm1 + SM_KWS;
    float* vsc = sm1 + SM_VSC;
    float* vsh = sm1 + SM_VSH;
    float* kk  = sm1 + SM_KK;
    float* ps  = sm1 + SM_PS;
    float* pm  = sm1 + SM_PM;

    const int tid = threadIdx.x;
    const int wid = tid >> 5, lane = tid & 31;
    const int g = lane >> 2, t = lane & 3;
    const int s = blockIdx.z, n = blockIdx.y, blk = blockIdx.x;
    const int e0 = blk * P1;
    const float* x = (s == 0 ? rgb : ir) + (size_t)n * CC * HW;

    // ---- fill x tile (cvt to tf32), coalesced float4 ----
    #pragma unroll
    for (int i = 0; i < 16; i++) {
        int idx = tid + i * 256;            // 4096 float4
        int r = idx >> 6, c4 = idx & 63;
        float4 v = *reinterpret_cast<const float4*>(x + (size_t)r * HW + e0 + (c4 << 2));
        uint4 u = make_uint4(tf32_(v.x), tf32_(v.y), tf32_(v.z), tf32_(v.w));
        *reinterpret_cast<uint4*>(xs + r * XSTR + (c4 << 2)) = u;
    }
    for (int idx = tid; idx < 4096; idx += 256) {
        int o = idx >> 6, c = idx & 63;
        wa[o * WSTR + c] = tf32_(conv_w[idx]);
        wb[o * WSTR + c] = tf32_(val_w[idx]);
    }
    if (tid < 64) {
        kws[tid] = key_w[tid];
        float sc = val_g[tid] * rsqrtf(val_v[tid] + EPS);
        vsc[tid] = sc; vsh[tid] = val_b[tid] - val_m[tid] * sc;
    }
    __syncthreads();

    const int pixbase = wid * 32;
    float acc[16][4];

    // ================= phase A: xc conv =================
    #pragma unroll
    for (int i = 0; i < 16; i++) { acc[i][0]=0.f; acc[i][1]=0.f; acc[i][2]=0.f; acc[i][3]=0.f; }
    gemm_tile(xs, wa, acc, pixbase, g, t);

    // epilogue A: per-warp channel sum/max over 32 pixels
    #pragma unroll
    for (int mt = 0; mt < 4; mt++) {
        float slo = 0.f, shi = 0.f, mlo = -3.0e38f, mhi = -3.0e38f;
        #pragma unroll
        for (int nt = 0; nt < 4; nt++) {
            float c0 = acc[mt*4+nt][0], c1 = acc[mt*4+nt][1];
            float c2 = acc[mt*4+nt][2], c3 = acc[mt*4+nt][3];
            slo += c0 + c1; shi += c2 + c3;
            mlo = fmaxf(mlo, fmaxf(c0, c1));
            mhi = fmaxf(mhi, fmaxf(c2, c3));
        }
        #pragma unroll
        for (int off = 1; off < 4; off <<= 1) {
            slo += __shfl_xor_sync(0xffffffffu, slo, off);
            shi += __shfl_xor_sync(0xffffffffu, shi, off);
            mlo = fmaxf(mlo, __shfl_xor_sync(0xffffffffu, mlo, off));
            mhi = fmaxf(mhi, __shfl_xor_sync(0xffffffffu, mhi, off));
        }
        if (t == 0) {
            ps[wid * 64 + mt * 16 + g]     = slo;
            ps[wid * 64 + mt * 16 + g + 8] = shi;
            pm[wid * 64 + mt * 16 + g]     = mlo;
            pm[wid * 64 + mt * 16 + g + 8] = mhi;
        }
    }

    // ---- key conv: one pixel per thread (reads tf32 bits as float) ----
    {
        const float* xf = reinterpret_cast<const float*>(xs);
        float ka = 0.f;
        #pragma unroll 8
        for (int c = 0; c < CC; c++) ka = fmaf(kws[c], xf[c * XSTR + tid], ka);
        float kscale = key_g[0] * rsqrtf(key_v[0] + EPS);
        float kbias = key_b[0] - key_m[0] * kscale;
        float kv = siluf_(ka * kscale + kbias);
        kk[tid] = kv;
        g_k[(size_t)(s * NN + n) * HW + e0 + tid] = kv;
    }
    __syncthreads();

    // block-level finals: channels by warps 0-1, key softmax by warp 2
    if (tid < 64) {
        float sv = 0.f, mv = -3.0e38f;
        #pragma unroll
        for (int w = 0; w < 8; w++) {
            sv += ps[w * 64 + tid];
            mv = fmaxf(mv, pm[w * 64 + tid]);
        }
        size_t b = ((size_t)(s * NN + n) * NB1 + blk) * CC + tid;
        g_psum[b] = sv; g_pmax[b] = mv;
    }
    if (wid == 2) {
        float m = kk[lane];
        #pragma unroll
        for (int i = 1; i < 8; i++) m = fmaxf(m, kk[lane + 32 * i]);
        #pragma unroll
        for (int off = 16; off; off >>= 1) m = fmaxf(m, __shfl_xor_sync(0xffffffffu, m, off));
        float z = 0.f;
        #pragma unroll
        for (int i = 0; i < 8; i++) z += fexp_(kk[lane + 32 * i] - m);
        #pragma unroll
        for (int off = 16; off; off >>= 1) z += __shfl_xor_sync(0xffffffffu, z, off);
        if (lane == 0) { int b = (s * NN + n) * NB1 + blk; g_pkm[b] = m; g_pkz[b] = z; }
    }

    // ================= phase B: val conv =================
    #pragma unroll
    for (int i = 0; i < 16; i++) { acc[i][0]=0.f; acc[i][1]=0.f; acc[i][2]=0.f; acc[i][3]=0.f; }
    gemm_tile(xs, wb, acc, pixbase, g, t);

    __syncthreads();   // all warps done reading xs — safe to overwrite with vals
    float* vals = sm1 + SM_X;   // [256 pix][VSTR]
    #pragma unroll
    for (int mt = 0; mt < 4; mt++) {
        int o  = mt * 16 + g;
        int o2 = o + 8;
        float sc = vsc[o],  sh = vsh[o];
        float sc2 = vsc[o2], sh2 = vsh[o2];
        #pragma unroll
        for (int nt = 0; nt < 4; nt++) {
            int p0 = pixbase + nt * 8 + 2 * t;
            vals[p0 * VSTR + o]        = siluf_(fmaf(acc[mt*4+nt][0], sc, sh));
            vals[(p0 + 1) * VSTR + o]  = siluf_(fmaf(acc[mt*4+nt][1], sc, sh));
            vals[p0 * VSTR + o2]       = siluf_(fmaf(acc[mt*4+nt][2], sc2, sh2));
            vals[(p0 + 1) * VSTR + o2] = siluf_(fmaf(acc[mt*4+nt][3], sc2, sh2));
        }
    }
    __syncthreads();
    // coalesced bf16 store: one pixel per thread, 64 ch = 128B
    {
        const float4* vrow = reinterpret_cast<const float4*>(vals + tid * VSTR);
        uint4* vo = reinterpret_cast<uint4*>(g_val + ((size_t)(s * NN + n) * HW + e0 + tid) * CC);
        #pragma unroll
        for (int i = 0; i < 8; i++) {
            float4 a = vrow[2 * i], b = vrow[2 * i + 1];
            __nv_bfloat162 p0 = __float22bfloat162_rn(make_float2(a.x, a.y));
            __nv_bfloat162 p1 = __float22bfloat162_rn(make_float2(a.z, a.w));
            __nv_bfloat162 p2 = __float22bfloat162_rn(make_float2(b.x, b.y));
            __nv_bfloat162 p3 = __float22bfloat162_rn(make_float2(b.z, b.w));
            uint4 u;
            u.x = *reinterpret_cast<unsigned*>(&p0);
            u.y = *reinterpret_cast<unsigned*>(&p1);
            u.z = *reinterpret_cast<unsigned*>(&p2);
            u.w = *reinterpret_cast<unsigned*>(&p3);
            vo[i] = u;
        }
    }
}

// ---------------- block-of-64 reductions ----------------
__device__ __forceinline__ float blk64_max(float v, float* red, int c) {
    red[c] = v; __syncthreads();
    for (int st = 32; st >= 1; st >>= 1) { if (c < st) red[c] = fmaxf(red[c], red[c + st]); __syncthreads(); }
    float r = red[0]; __syncthreads(); return r;
}
__device__ __forceinline__ float blk64_sum(float v, float* red, int c) {
    red[c] = v; __syncthreads();
    for (int st = 32; st >= 1; st >>= 1) { if (c < st) red[c] += red[c + st]; __syncthreads(); }
    float r = red[0]; __syncthreads(); return r;
}

// ---------------- kernel 2: finalize stats (avg/mx softmax, key M/Z) ----------------
__global__ __launch_bounds__(64) void k2(const float* __restrict__ conv_b)
{
    const int n = blockIdx.x, s = blockIdx.y, c = threadIdx.x;
    __shared__ float red[64];
    const size_t base = (size_t)(s * NN + n) * NB1;

    float sv = 0.f, mv = -3.0e38f;
    for (int b = 0; b < NB1; b++) {
        sv += g_psum[(base + b) * CC + c];
        mv = fmaxf(mv, g_pmax[(base + b) * CC + c]);
    }
    float mean = sv * (1.f / HW) + conv_b[c];
    float mx   = mv + conv_b[c];

    float am = blk64_max(mean, red, c);
    float ea = fexp_(mean - am);
    float za = blk64_sum(ea, red, c);
    g_avg[(s * NN + n) * CC + c] = ea / za;

    float mm = blk64_max(mx, red, c);
    float em = fexp_(mx - mm);
    float zm = blk64_sum(em, red, c);
    g_mx[(s * NN + n) * CC + c] = em / zm;

    float km = -3.0e38f;
    for (int b = c; b < NB1; b += 64) km = fmaxf(km, g_pkm[base + b]);
    float M = blk64_max(km, red, c);
    float z = 0.f;
    for (int b = c; b < NB1; b += 64) z += g_pkz[base + b] * fexp_(g_pkm[base + b] - M);
    float Z = blk64_sum(z, red, c);
    if (c == 0) { g_kM[s * NN + n] = M; g_kZ[s * NN + n] = Z; }
}

// ---------------- kernel 2.5: fea partials = sum_e val[1-s]*softkey[s] ----------------
__global__ __launch_bounds__(256) void k25()
{
    const int s = blockIdx.z, n = blockIdx.y, ch = blockIdx.x;
    const int tid = threadIdx.x;
    const int e0 = ch * CH25;
    __shared__ float wk[CH25];
    __shared__ float pr[512];

    const float M = g_kM[s * NN + n];
    const float invZ = __fdividef(1.f, g_kZ[s * NN + n]);
    const float* kp = g_k + (size_t)(s * NN + n) * HW + e0;
    for (int i = tid; i < CH25; i += 256) wk[i] = fexp_(kp[i] - M) * invZ;
    __syncthreads();

    const int cp = tid & 31, r = tid >> 5;   // 32 channel-pairs, 8 rows
    const __nv_bfloat162* vp = reinterpret_cast<const __nv_bfloat162*>(
        g_val + ((size_t)((1 - s) * NN + n) * HW + e0) * CC);
    float ax = 0.f, ay = 0.f;
    for (int i = r; i < CH25; i += 8) {
        float2 v = __bfloat1622float2(vp[(size_t)i * 32 + cp]);
        float w = wk[i];
        ax = fmaf(v.x, w, ax);
        ay = fmaf(v.y, w, ay);
    }
    pr[r * 64 + 2 * cp]     = ax;
    pr[r * 64 + 2 * cp + 1] = ay;
    __syncthreads();
    if (tid < 64) {
        float f = 0.f;
        #pragma unroll
        for (int w = 0; w < 8; w++) f += pr[w * 64 + tid];
        g_feap[((size_t)(s * NN + n) * NB25 + ch) * CC + tid] = f;
    }
}

// ---------------- kernel 2.75: gate = sigmoid(LN(fea @ convb^T)) ----------------
__global__ __launch_bounds__(64) void k27(
    const float* __restrict__ convb_w, const float* __restrict__ ln_g, const float* __restrict__ ln_b)
{
    const int n = blockIdx.x, s = blockIdx.y, c = threadIdx.x;
    __shared__ float feas[64];
    __shared__ float red[64];
    const size_t base = (size_t)(s * NN + n) * NB25 * CC;
    float f = 0.f;
    for (int b = 0; b < NB25; b++) f += g_feap[base + (size_t)b * CC + c];
    feas[c] = f; __syncthreads();

    float g = 0.f;
    #pragma unroll 8
    for (int j = 0; j < CC; j++) g = fmaf(convb_w[c * CC + j], feas[j], g);

    float mu  = blk64_sum(g, red, c) * (1.f / CC);
    float d   = g - mu;
    float var = blk64_sum(d * d, red, c) * (1.f / CC);
    float zz  = d * rsqrtf(var + EPS) * ln_g[c] + ln_b[c];
    g_gate[(s * NN + n) * CC + c] = sigmoidf_(zz);
}

// ---------------- kernel 3: output = gate * half + me ----------------
__global__ __launch_bounds__(256) void k3(
    const float* __restrict__ rgb, const float* __restrict__ ir, float* __restrict__ out,
    const float* __restrict__ half_w,
    const float* __restrict__ half_g, const float* __restrict__ half_b,
    const float* __restrict__ half_m, const float* __restrict__ half_v)
{
    const int s = blockIdx.z, n = blockIdx.y;
    const int e0 = blockIdx.x * P3;
    const int tid = threadIdx.x;
    __shared__ __align__(16) float avs[64];
    __shared__ __align__(16) float mxs[64];
    __shared__ __align__(16) float gts[64];
    if (tid < 64) {
        int i = (s * NN + n) * CC + tid;
        avs[tid] = g_avg[i]; mxs[tid] = g_mx[i]; gts[tid] = g_gate[i];
    }
    __syncthreads();

    const uint4* vp = reinterpret_cast<const uint4*>(
        g_val + ((size_t)((1 - s) * NN + n) * HW + e0 + tid) * CC);
    float aA = 0.f, aM = 0.f;
    #pragma unroll
    for (int q = 0; q < 8; q++) {
        uint4 u = vp[q];
        #pragma unroll
        for (int h = 0; h < 4; h++) {
            unsigned uw = (h == 0 ? u.x : h == 1 ? u.y : h == 2 ? u.z : u.w);
            float2 v = __bfloat1622float2(*reinterpret_cast<__nv_bfloat162*>(&uw));
            int c = q * 8 + h * 2;
            aA = fmaf(v.x, avs[c], fmaf(v.y, avs[c + 1], aA));
            aM = fmaf(v.x, mxs[c], fmaf(v.y, mxs[c + 1], aM));
        }
    }
    float hs = half_g[0] * rsqrtf(half_v[0] + EPS);
    float hb = half_b[0] - half_m[0] * hs;
    float pre = half_w[0] * aA + half_w[1] * aM;
    float hlf = siluf_(pre * hs + hb);

    const float* xme = (s == 0 ? rgb : ir) + (size_t)n * CC * HW;
    float* op = out + (size_t)(s * NN + n) * CC * HW;
    #pragma unroll 4
    for (int c = 0; c < CC; c++) {
        size_t idx = (size_t)c * HW + e0 + tid;
        op[idx] = fmaf(gts[c], hlf, xme[idx]);
    }
}

// ---------------- launch ----------------
extern "C" void kernel_launch(void* const* d_in, const int* in_sizes, int n_in,
                              void* d_out, int out_size)
{
    const float* rgb     = (const float*)d_in[0];
    const float* ir      = (const float*)d_in[1];
    const float* conv_w  = (const float*)d_in[2];
    const float* conv_b  = (const float*)d_in[3];
    const float* key_w   = (const float*)d_in[4];
    const float* key_g   = (const float*)d_in[5];
    const float* key_b   = (const float*)d_in[6];
    const float* key_m   = (const float*)d_in[7];
    const float* key_v   = (const float*)d_in[8];
    const float* val_w   = (const float*)d_in[9];
    const float* val_g   = (const float*)d_in[10];
    const float* val_b   = (const float*)d_in[11];
    const float* val_m   = (const float*)d_in[12];
    const float* val_v   = (const float*)d_in[13];
    const float* convb_w = (const float*)d_in[14];
    const float* half_w  = (const float*)d_in[15];
    const float* half_g  = (const float*)d_in[16];
    const float* half_b  = (const float*)d_in[17];
    const float* half_m  = (const float*)d_in[18];
    const float* half_v  = (const float*)d_in[19];
    const float* ln_g    = (const float*)d_in[20];
    const float* ln_b    = (const float*)d_in[21];
    float* out = (float*)d_out;

    const size_t smem1 = SM1_FLOATS * sizeof(float);   // 110336 B
    cudaFuncSetAttribute(k1, cudaFuncAttributeMaxDynamicSharedMemorySize, (int)smem1);

    k1<<<dim3(NB1, NN, 2), 256, smem1>>>(rgb, ir, conv_w, val_w, key_w,
                                         key_g, key_b, key_m, key_v,
                                         val_g, val_b, val_m, val_v);
    k2<<<dim3(NN, 2), 64>>>(conv_b);
    k25<<<dim3(NB25, NN, 2), 256>>>();
    k27<<<dim3(NN, 2), 64>>>(convb_w, ln_g, ln_b);
    k3<<<dim3(NB3, NN, 2), 256>>>(rgb, ir, out, half_w, half_g, half_b, half_m, half_v);
}

// round 6
// speedup vs baseline: 2.3432x; 1.0238x over previous
#include <cuda_runtime.h>
#include <cuda_bf16.h>
#include <math.h>

#define EPS 1e-5f
#define CC 64
#define NN 8
#define HW 65536
#define P1 256
#define NB1 (HW/P1)      /* 256 blocks for k1/k2 partials */
#define CH25 1024
#define NB25 (HW/CH25)   /* 64 */
#define P3 256
#define NB3 (HW/P3)      /* 256 */

// ---------------- scratch (__device__ globals; no allocation) ----------------
__device__ __nv_bfloat16 g_val[(size_t)2*NN*HW*CC];   // 134 MiB, [side][n][pix][c]
__device__ float g_k[2*NN*HW];                // silu'd key values
__device__ float g_psum[2*NN*NB1*CC];
__device__ float g_pmax[2*NN*NB1*CC];
__device__ float g_pkm[2*NN*NB1];
__device__ float g_pkz[2*NN*NB1];
__device__ float g_avg[2*NN*CC];
__device__ float g_mx[2*NN*CC];
__device__ float g_kM[2*NN];
__device__ float g_kZ[2*NN];
__device__ float g_feap[2*NN*NB25*CC];
__device__ float g_gate[2*NN*CC];

__device__ __forceinline__ float fexp_(float x){ return __expf(x); }
__device__ __forceinline__ float tanhf_(float x){
    float r; asm("tanh.approx.f32 %0, %1;" : "=f"(r) : "f"(x)); return r;
}
// sigmoid(x) = 0.5*tanh(x/2) + 0.5  (1 MUFU instead of EX2+RCP)
__device__ __forceinline__ float sigmoidf_(float x){ return fmaf(0.5f, tanhf_(0.5f * x), 0.5f); }
__device__ __forceinline__ float siluf_(float x){ return x * sigmoidf_(x); }

__device__ __forceinline__ unsigned tf32_(float f){
    unsigned u; asm("cvt.rna.tf32.f32 %0, %1;" : "=r"(u) : "f"(f)); return u;
}

// m16n8k8 tf32 mma, f32 accumulate
#define MMA_TF32(d, a, b) \
    asm volatile("mma.sync.aligned.m16n8k8.row.col.f32.tf32.tf32.f32 " \
        "{%0,%1,%2,%3}, {%4,%5,%6,%7}, {%8,%9}, {%0,%1,%2,%3};" \
        : "+f"((d)[0]), "+f"((d)[1]), "+f"((d)[2]), "+f"((d)[3]) \
        : "r"((a)[0]), "r"((a)[1]), "r"((a)[2]), "r"((a)[3]), \
          "r"((b)[0]), "r"((b)[1]))

// ---------------- kernel 1 smem layout (floats) ----------------
#define XSTR 264          /* x tile row stride (64 rows) */
#define WSTR 68           /* weight tile row stride */
#define VSTR 68           /* staged val row stride */
#define SM_X    0         /* x tile (fp32 bits) 64*264=16896; reused as vals 256*68=17408 */
#define SM_WA   17408     /* conv_w tf32, 64*68=4352 */
#define SM_WB   21760     /* val_w tf32 */
#define SM_KWS  26112
#define SM_VSC  26176
#define SM_VSH  26240
#define SM_KK   26304     /* 256 key values */
#define SM_PS   26560     /* per-warp channel sums [8][64] */
#define SM_PM   27072     /* per-warp channel maxes [8][64] */
#define SM1_FLOATS 27584  /* 110336 bytes */

extern __shared__ float sm1[];

__device__ __forceinline__ void gemm_tile(const unsigned* __restrict__ xs,
                                          const unsigned* __restrict__ wp,
                                          float acc[16][4], int pixbase, int g, int t)
{
    #pragma unroll
    for (int ks = 0; ks < 8; ks++) {
        unsigned bfr[4][2];
        #pragma unroll
        for (int nt = 0; nt < 4; nt++) {
            int pcol = pixbase + nt * 8 + g;
            bfr[nt][0] = xs[(ks * 8 + t) * XSTR + pcol];
            bfr[nt][1] = xs[(ks * 8 + t + 4) * XSTR + pcol];
        }
        unsigned afr[4][4];
        #pragma unroll
        for (int mt = 0; mt < 4; mt++) {
            int row = mt * 16 + g;
            afr[mt][0] = wp[row * WSTR + ks * 8 + t];
            afr[mt][1] = wp[(row + 8) * WSTR + ks * 8 + t];
            afr[mt][2] = wp[row * WSTR + ks * 8 + t + 4];
            afr[mt][3] = wp[(row + 8) * WSTR + ks * 8 + t + 4];
        }
        #pragma unroll
        for (int mt = 0; mt < 4; mt++)
            #pragma unroll
            for (int nt = 0; nt < 4; nt++)
                MMA_TF32(acc[mt * 4 + nt], afr[mt], bfr[nt]);
    }
}

__global__ __launch_bounds__(256) void k1(
    const float* __restrict__ rgb, const float* __restrict__ ir,
    const float* __restrict__ conv_w, const float* __restrict__ val_w,
    const float* __restrict__ key_w,
    const float* __restrict__ key_g, const float* __restrict__ key_b,
    const float* __restrict__ key_m, const float* __restrict__ key_v,
    const float* __restrict__ val_g, const float* __restrict__ val_b,
    const float* __restrict__ val_m, const float* __restrict__ val_v)
{
    unsigned* xs = reinterpret_cast<unsigned*>(sm1 + SM_X);
    unsigned* wa = reinterpret_cast<unsigned*>(sm1 + SM_WA);
    unsigned* wb = reinterpret_cast<unsigned*>(sm1 + SM_WB);
    float* kws = sm1 + SM_KWS;
    float* vsc = sm1 + SM_VSC;
    float* vsh = sm1 + SM_VSH;
    float* kk  = sm1 + SM_KK;
    float* ps  = sm1 + SM_PS;
    float* pm  = sm1 + SM_PM;

    const int tid = threadIdx.x;
    const int wid = tid >> 5, lane = tid & 31;
    const int g = lane >> 2, t = lane & 3;
    const int s = blockIdx.z, n = blockIdx.y, blk = blockIdx.x;
    const int e0 = blk * P1;
    const float* x = (s == 0 ? rgb : ir) + (size_t)n * CC * HW;

    // ---- fill x tile: raw fp32 bits (tf32 mma ignores low mantissa bits) ----
    #pragma unroll
    for (int i = 0; i < 16; i++) {
        int idx = tid + i * 256;            // 4096 float4
        int r = idx >> 6, c4 = idx & 63;
        uint4 u = *reinterpret_cast<const uint4*>(x + (size_t)r * HW + e0 + (c4 << 2));
        *reinterpret_cast<uint4*>(xs + r * XSTR + (c4 << 2)) = u;
    }
    for (int idx = tid; idx < 4096; idx += 256) {
        int o = idx >> 6, c = idx & 63;
        wa[o * WSTR + c] = tf32_(conv_w[idx]);
        wb[o * WSTR + c] = tf32_(val_w[idx]);
    }
    if (tid < 64) {
        kws[tid] = key_w[tid];
        float sc = val_g[tid] * rsqrtf(val_v[tid] + EPS);
        vsc[tid] = sc; vsh[tid] = val_b[tid] - val_m[tid] * sc;
    }
    __syncthreads();

    const int pixbase = wid * 32;
    float acc[16][4];

    // ================= phase A: xc conv =================
    #pragma unroll
    for (int i = 0; i < 16; i++) { acc[i][0]=0.f; acc[i][1]=0.f; acc[i][2]=0.f; acc[i][3]=0.f; }
    gemm_tile(xs, wa, acc, pixbase, g, t);

    // epilogue A: per-warp channel sum/max over 32 pixels
    #pragma unroll
    for (int mt = 0; mt < 4; mt++) {
        float slo = 0.f, shi = 0.f, mlo = -3.0e38f, mhi = -3.0e38f;
        #pragma unroll
        for (int nt = 0; nt < 4; nt++) {
            float c0 = acc[mt*4+nt][0], c1 = acc[mt*4+nt][1];
            float c2 = acc[mt*4+nt][2], c3 = acc[mt*4+nt][3];
            slo += c0 + c1; shi += c2 + c3;
            mlo = fmaxf(mlo, fmaxf(c0, c1));
            mhi = fmaxf(mhi, fmaxf(c2, c3));
        }
        #pragma unroll
        for (int off = 1; off < 4; off <<= 1) {
            slo += __shfl_xor_sync(0xffffffffu, slo, off);
            shi += __shfl_xor_sync(0xffffffffu, shi, off);
            mlo = fmaxf(mlo, __shfl_xor_sync(0xffffffffu, mlo, off));
            mhi = fmaxf(mhi, __shfl_xor_sync(0xffffffffu, mhi, off));
        }
        if (t == 0) {
            ps[wid * 64 + mt * 16 + g]     = slo;
            ps[wid * 64 + mt * 16 + g + 8] = shi;
            pm[wid * 64 + mt * 16 + g]     = mlo;
            pm[wid * 64 + mt * 16 + g + 8] = mhi;
        }
    }

    // ---- key conv: one pixel per thread (exact fp32 x) ----
    {
        const float* xf = reinterpret_cast<const float*>(xs);
        float ka = 0.f;
        #pragma unroll 8
        for (int c = 0; c < CC; c++) ka = fmaf(kws[c], xf[c * XSTR + tid], ka);
        float kscale = key_g[0] * rsqrtf(key_v[0] + EPS);
        float kbias = key_b[0] - key_m[0] * kscale;
        float kv = siluf_(ka * kscale + kbias);
        kk[tid] = kv;
        g_k[(size_t)(s * NN + n) * HW + e0 + tid] = kv;
    }
    __syncthreads();

    // block-level finals: channels by warps 0-1, key softmax by warp 2
    if (tid < 64) {
        float sv = 0.f, mv = -3.0e38f;
        #pragma unroll
        for (int w = 0; w < 8; w++) {
            sv += ps[w * 64 + tid];
            mv = fmaxf(mv, pm[w * 64 + tid]);
        }
        size_t b = ((size_t)(s * NN + n) * NB1 + blk) * CC + tid;
        g_psum[b] = sv; g_pmax[b] = mv;
    }
    if (wid == 2) {
        float m = kk[lane];
        #pragma unroll
        for (int i = 1; i < 8; i++) m = fmaxf(m, kk[lane + 32 * i]);
        #pragma unroll
        for (int off = 16; off; off >>= 1) m = fmaxf(m, __shfl_xor_sync(0xffffffffu, m, off));
        float z = 0.f;
        #pragma unroll
        for (int i = 0; i < 8; i++) z += fexp_(kk[lane + 32 * i] - m);
        #pragma unroll
        for (int off = 16; off; off >>= 1) z += __shfl_xor_sync(0xffffffffu, z, off);
        if (lane == 0) { int b = (s * NN + n) * NB1 + blk; g_pkm[b] = m; g_pkz[b] = z; }
    }

    // ================= phase B: val conv =================
    #pragma unroll
    for (int i = 0; i < 16; i++) { acc[i][0]=0.f; acc[i][1]=0.f; acc[i][2]=0.f; acc[i][3]=0.f; }
    gemm_tile(xs, wb, acc, pixbase, g, t);

    __syncthreads();   // all warps done reading xs — safe to overwrite with vals
    float* vals = sm1 + SM_X;   // [256 pix][VSTR]
    #pragma unroll
    for (int mt = 0; mt < 4; mt++) {
        int o  = mt * 16 + g;
        int o2 = o + 8;
        float sc = vsc[o],  sh = vsh[o];
        float sc2 = vsc[o2], sh2 = vsh[o2];
        #pragma unroll
        for (int nt = 0; nt < 4; nt++) {
            int p0 = pixbase + nt * 8 + 2 * t;
            vals[p0 * VSTR + o]        = siluf_(fmaf(acc[mt*4+nt][0], sc, sh));
            vals[(p0 + 1) * VSTR + o]  = siluf_(fmaf(acc[mt*4+nt][1], sc, sh));
            vals[p0 * VSTR + o2]       = siluf_(fmaf(acc[mt*4+nt][2], sc2, sh2));
            vals[(p0 + 1) * VSTR + o2] = siluf_(fmaf(acc[mt*4+nt][3], sc2, sh2));
        }
    }
    __syncthreads();
    // coalesced bf16 store: one pixel per thread, 64 ch = 128B
    {
        const float4* vrow = reinterpret_cast<const float4*>(vals + tid * VSTR);
        uint4* vo = reinterpret_cast<uint4*>(g_val + ((size_t)(s * NN + n) * HW + e0 + tid) * CC);
        #pragma unroll
        for (int i = 0; i < 8; i++) {
            float4 a = vrow[2 * i], b = vrow[2 * i + 1];
            __nv_bfloat162 p0 = __float22bfloat162_rn(make_float2(a.x, a.y));
            __nv_bfloat162 p1 = __float22bfloat162_rn(make_float2(a.z, a.w));
            __nv_bfloat162 p2 = __float22bfloat162_rn(make_float2(b.x, b.y));
            __nv_bfloat162 p3 = __float22bfloat162_rn(make_float2(b.z, b.w));
            uint4 u;
            u.x = *reinterpret_cast<unsigned*>(&p0);
            u.y = *reinterpret_cast<unsigned*>(&p1);
            u.z = *reinterpret_cast<unsigned*>(&p2);
            u.w = *reinterpret_cast<unsigned*>(&p3);
            vo[i] = u;
        }
    }
}

// ---------------- block-of-64 reductions ----------------
__device__ __forceinline__ float blk64_max(float v, float* red, int c) {
    red[c] = v; __syncthreads();
    for (int st = 32; st >= 1; st >>= 1) { if (c < st) red[c] = fmaxf(red[c], red[c + st]); __syncthreads(); }
    float r = red[0]; __syncthreads(); return r;
}
__device__ __forceinline__ float blk64_sum(float v, float* red, int c) {
    red[c] = v; __syncthreads();
    for (int st = 32; st >= 1; st >>= 1) { if (c < st) red[c] += red[c + st]; __syncthreads(); }
    float r = red[0]; __syncthreads(); return r;
}

// ---------------- kernel 2: finalize stats (avg/mx softmax, key M/Z) ----------------
__global__ __launch_bounds__(64) void k2(const float* __restrict__ conv_b)
{
    const int n = blockIdx.x, s = blockIdx.y, c = threadIdx.x;
    __shared__ float red[64];
    const size_t base = (size_t)(s * NN + n) * NB1;

    float sv = 0.f, mv = -3.0e38f;
    for (int b = 0; b < NB1; b++) {
        sv += g_psum[(base + b) * CC + c];
        mv = fmaxf(mv, g_pmax[(base + b) * CC + c]);
    }
    float mean = sv * (1.f / HW) + conv_b[c];
    float mx   = mv + conv_b[c];

    float am = blk64_max(mean, red, c);
    float ea = fexp_(mean - am);
    float za = blk64_sum(ea, red, c);
    g_avg[(s * NN + n) * CC + c] = ea / za;

    float mm = blk64_max(mx, red, c);
    float em = fexp_(mx - mm);
    float zm = blk64_sum(em, red, c);
    g_mx[(s * NN + n) * CC + c] = em / zm;

    float km = -3.0e38f;
    for (int b = c; b < NB1; b += 64) km = fmaxf(km, g_pkm[base + b]);
    float M = blk64_max(km, red, c);
    float z = 0.f;
    for (int b = c; b < NB1; b += 64) z += g_pkz[base + b] * fexp_(g_pkm[base + b] - M);
    float Z = blk64_sum(z, red, c);
    if (c == 0) { g_kM[s * NN + n] = M; g_kZ[s * NN + n] = Z; }
}

// ---------------- kernel 2.5: fea partials = sum_e val[1-s]*softkey[s] ----------------
__global__ __launch_bounds__(256) void k25()
{
    const int s = blockIdx.z, n = blockIdx.y, ch = blockIdx.x;
    const int tid = threadIdx.x;
    const int e0 = ch * CH25;
    __shared__ float wk[CH25];
    __shared__ float pr[512];

    const float M = g_kM[s * NN + n];
    const float invZ = __fdividef(1.f, g_kZ[s * NN + n]);
    const float* kp = g_k + (size_t)(s * NN + n) * HW + e0;
    for (int i = tid; i < CH25; i += 256) wk[i] = fexp_(kp[i] - M) * invZ;
    __syncthreads();

    const int cp = tid & 31, r = tid >> 5;   // 32 channel-pairs, 8 rows
    const __nv_bfloat162* vp = reinterpret_cast<const __nv_bfloat162*>(
        g_val + ((size_t)((1 - s) * NN + n) * HW + e0) * CC);
    float ax = 0.f, ay = 0.f;
    for (int i = r; i < CH25; i += 8) {
        float2 v = __bfloat1622float2(vp[(size_t)i * 32 + cp]);
        float w = wk[i];
        ax = fmaf(v.x, w, ax);
        ay = fmaf(v.y, w, ay);
    }
    pr[r * 64 + 2 * cp]     = ax;
    pr[r * 64 + 2 * cp + 1] = ay;
    __syncthreads();
    if (tid < 64) {
        float f = 0.f;
        #pragma unroll
        for (int w = 0; w < 8; w++) f += pr[w * 64 + tid];
        g_feap[((size_t)(s * NN + n) * NB25 + ch) * CC + tid] = f;
    }
}

// ---------------- kernel 2.75: gate = sigmoid(LN(fea @ convb^T)) ----------------
__global__ __launch_bounds__(64) void k27(
    const float* __restrict__ convb_w, const float* __restrict__ ln_g, const float* __restrict__ ln_b)
{
    const int n = blockIdx.x, s = blockIdx.y, c = threadIdx.x;
    __shared__ float feas[64];
    __shared__ float red[64];
    const size_t base = (size_t)(s * NN + n) * NB25 * CC;
    float f = 0.f;
    for (int b = 0; b < NB25; b++) f += g_feap[base + (size_t)b * CC + c];
    feas[c] = f; __syncthreads();

    float g = 0.f;
    #pragma unroll 8
    for (int j = 0; j < CC; j++) g = fmaf(convb_w[c * CC + j], feas[j], g);

    float mu  = blk64_sum(g, red, c) * (1.f / CC);
    float d   = g - mu;
    float var = blk64_sum(d * d, red, c) * (1.f / CC);
    float zz  = d * rsqrtf(var + EPS) * ln_g[c] + ln_b[c];
    g_gate[(s * NN + n) * CC + c] = sigmoidf_(zz);
}

// ---------------- kernel 3: output = gate * half + me ----------------
__global__ __launch_bounds__(256) void k3(
    const float* __restrict__ rgb, const float* __restrict__ ir, float* __restrict__ out,
    const float* __restrict__ half_w,
    const float* __restrict__ half_g, const float* __restrict__ half_b,
    const float* __restrict__ half_m, const float* __restrict__ half_v)
{
    const int s = blockIdx.z, n = blockIdx.y;
    const int e0 = blockIdx.x * P3;
    const int tid = threadIdx.x;
    __shared__ __align__(16) float avs[64];
    __shared__ __align__(16) float mxs[64];
    __shared__ __align__(16) float gts[64];
    if (tid < 64) {
        int i = (s * NN + n) * CC + tid;
        avs[tid] = g_avg[i]; mxs[tid] = g_mx[i]; gts[tid] = g_gate[i];
    }
    __syncthreads();

    const uint4* vp = reinterpret_cast<const uint4*>(
        g_val + ((size_t)((1 - s) * NN + n) * HW + e0 + tid) * CC);
    float aA = 0.f, aM = 0.f;
    #pragma unroll
    for (int q = 0; q < 8; q++) {
        uint4 u = vp[q];
        #pragma unroll
        for (int h = 0; h < 4; h++) {
            unsigned uw = (h == 0 ? u.x : h == 1 ? u.y : h == 2 ? u.z : u.w);
            float2 v = __bfloat1622float2(*reinterpret_cast<__nv_bfloat162*>(&uw));
            int c = q * 8 + h * 2;
            aA = fmaf(v.x, avs[c], fmaf(v.y, avs[c + 1], aA));
            aM = fmaf(v.x, mxs[c], fmaf(v.y, mxs[c + 1], aM));
        }
    }
    float hs = half_g[0] * rsqrtf(half_v[0] + EPS);
    float hb = half_b[0] - half_m[0] * hs;
    float pre = half_w[0] * aA + half_w[1] * aM;
    float hlf = siluf_(pre * hs + hb);

    const float* xme = (s == 0 ? rgb : ir) + (size_t)n * CC * HW;
    float* op = out + (size_t)(s * NN + n) * CC * HW;
    #pragma unroll 4
    for (int c = 0; c < CC; c++) {
        size_t idx = (size_t)c * HW + e0 + tid;
        op[idx] = fmaf(gts[c], hlf, xme[idx]);
    }
}

// ---------------- launch ----------------
extern "C" void kernel_launch(void* const* d_in, const int* in_sizes, int n_in,
                              void* d_out, int out_size)
{
    const float* rgb     = (const float*)d_in[0];
    const float* ir      = (const float*)d_in[1];
    const float* conv_w  = (const float*)d_in[2];
    const float* conv_b  = (const float*)d_in[3];
    const float* key_w   = (const float*)d_in[4];
    const float* key_g   = (const float*)d_in[5];
    const float* key_b   = (const float*)d_in[6];
    const float* key_m   = (const float*)d_in[7];
    const float* key_v   = (const float*)d_in[8];
    const float* val_w   = (const float*)d_in[9];
    const float* val_g   = (const float*)d_in[10];
    const float* val_b   = (const float*)d_in[11];
    const float* val_m   = (const float*)d_in[12];
    const float* val_v   = (const float*)d_in[13];
    const float* convb_w = (const float*)d_in[14];
    const float* half_w  = (const float*)d_in[15];
    const float* half_g  = (const float*)d_in[16];
    const float* half_b  = (const float*)d_in[17];
    const float* half_m  = (const float*)d_in[18];
    const float* half_v  = (const float*)d_in[19];
    const float* ln_g    = (const float*)d_in[20];
    const float* ln_b    = (const float*)d_in[21];
    float* out = (float*)d_out;

    const size_t smem1 = SM1_FLOATS * sizeof(float);   // 110336 B
    cudaFuncSetAttribute(k1, cudaFuncAttributeMaxDynamicSharedMemorySize, (int)smem1);

    k1<<<dim3(NB1, NN, 2), 256, smem1>>>(rgb, ir, conv_w, val_w, key_w,
                                         key_g, key_b, key_m, key_v,
                                         val_g, val_b, val_m, val_v);
    k2<<<dim3(NN, 2), 64>>>(conv_b);
    k25<<<dim3(NB25, NN, 2), 256>>>();
    k27<<<dim3(NN, 2), 64>>>(convb_w, ln_g, ln_b);
    k3<<<dim3(NB3, NN, 2), 256>>>(rgb, ir, out, half_w, half_g, half_b, half_m, half_v);
}

// round 7
// speedup vs baseline: 2.8495x; 1.2161x over previous
#include <cuda_runtime.h>
#include <cuda_bf16.h>
#include <math.h>

#define EPS 1e-5f
#define CC 64
#define NN 8
#define HW 65536
#define P1 256
#define NB1 (HW/P1)      /* 256 */
#define CH25 1024
#define NB25 (HW/CH25)   /* 64 */
#define P3 512
#define NB3 (HW/P3)      /* 128 */

// ---------------- scratch (__device__ globals; no allocation) ----------------
__device__ __nv_bfloat16 g_val[(size_t)2*NN*CC*HW];   // 134 MiB, [side][n][c][pix]
__device__ float g_k[2*NN*HW];
__device__ float g_psum[2*NN*NB1*CC];
__device__ float g_pmax[2*NN*NB1*CC];
__device__ float g_pkm[2*NN*NB1];
__device__ float g_pkz[2*NN*NB1];
__device__ float g_avg[2*NN*CC];
__device__ float g_mx[2*NN*CC];
__device__ float g_feap[2*NN*NB25*CC];
__device__ float g_gate[2*NN*CC];

__device__ __forceinline__ float fexp_(float x){ return __expf(x); }
__device__ __forceinline__ float tanhf_(float x){
    float r; asm("tanh.approx.f32 %0, %1;" : "=f"(r) : "f"(x)); return r;
}
__device__ __forceinline__ float sigmoidf_(float x){ return fmaf(0.5f, tanhf_(0.5f * x), 0.5f); }
__device__ __forceinline__ float siluf_(float x){ return x * sigmoidf_(x); }

__device__ __forceinline__ unsigned tf32_(float f){
    unsigned u; asm("cvt.rna.tf32.f32 %0, %1;" : "=r"(u) : "f"(f)); return u;
}

#define MMA_TF32(d, a, b) \
    asm volatile("mma.sync.aligned.m16n8k8.row.col.f32.tf32.tf32.f32 " \
        "{%0,%1,%2,%3}, {%4,%5,%6,%7}, {%8,%9}, {%0,%1,%2,%3};" \
        : "+f"((d)[0]), "+f"((d)[1]), "+f"((d)[2]), "+f"((d)[3]) \
        : "r"((a)[0]), "r"((a)[1]), "r"((a)[2]), "r"((a)[3]), \
          "r"((b)[0]), "r"((b)[1]))

// ---------------- kernel 1 smem layout (floats) ----------------
#define XSTR 264
#define WSTR 68
#define SM_X    0         /* x tile (fp32 bits) 64*264=16896 */
#define SM_WA   17408
#define SM_WB   21760
#define SM_KWS  26112
#define SM_VSC  26176
#define SM_VSH  26240
#define SM_KK   26304     /* 256 key values */
#define SM_PS   26560     /* per-warp channel sums [8][64] */
#define SM_PM   27072     /* per-warp channel maxes [8][64] */
#define SM1_FLOATS 27584  /* 110336 bytes */

extern __shared__ float sm1[];

__device__ __forceinline__ void gemm_tile(const unsigned* __restrict__ xs,
                                          const unsigned* __restrict__ wp,
                                          float acc[16][4], int pixbase, int g, int t)
{
    #pragma unroll
    for (int ks = 0; ks < 8; ks++) {
        unsigned bfr[4][2];
        #pragma unroll
        for (int nt = 0; nt < 4; nt++) {
            int pcol = pixbase + nt * 8 + g;
            bfr[nt][0] = xs[(ks * 8 + t) * XSTR + pcol];
            bfr[nt][1] = xs[(ks * 8 + t + 4) * XSTR + pcol];
        }
        unsigned afr[4][4];
        #pragma unroll
        for (int mt = 0; mt < 4; mt++) {
            int row = mt * 16 + g;
            afr[mt][0] = wp[row * WSTR + ks * 8 + t];
            afr[mt][1] = wp[(row + 8) * WSTR + ks * 8 + t];
            afr[mt][2] = wp[row * WSTR + ks * 8 + t + 4];
            afr[mt][3] = wp[(row + 8) * WSTR + ks * 8 + t + 4];
        }
        #pragma unroll
        for (int mt = 0; mt < 4; mt++)
            #pragma unroll
            for (int nt = 0; nt < 4; nt++)
                MMA_TF32(acc[mt * 4 + nt], afr[mt], bfr[nt]);
    }
}

__global__ __launch_bounds__(256) void k1(
    const float* __restrict__ rgb, const float* __restrict__ ir,
    const float* __restrict__ conv_w, const float* __restrict__ val_w,
    const float* __restrict__ key_w,
    const float* __restrict__ key_g, const float* __restrict__ key_b,
    const float* __restrict__ key_m, const float* __restrict__ key_v,
    const float* __restrict__ val_g, const float* __restrict__ val_b,
    const float* __restrict__ val_m, const float* __restrict__ val_v)
{
    unsigned* xs = reinterpret_cast<unsigned*>(sm1 + SM_X);
    unsigned* wa = reinterpret_cast<unsigned*>(sm1 + SM_WA);
    unsigned* wb = reinterpret_cast<unsigned*>(sm1 + SM_WB);
    float* kws = sm1 + SM_KWS;
    float* vsc = sm1 + SM_VSC;
    float* vsh = sm1 + SM_VSH;
    float* kk  = sm1 + SM_KK;
    float* ps  = sm1 + SM_PS;
    float* pm  = sm1 + SM_PM;

    const int tid = threadIdx.x;
    const int wid = tid >> 5, lane = tid & 31;
    const int g = lane >> 2, t = lane & 3;
    const int s = blockIdx.z, n = blockIdx.y, blk = blockIdx.x;
    const int e0 = blk * P1;
    const float* x = (s == 0 ? rgb : ir) + (size_t)n * CC * HW;

    // ---- x tile: raw fp32 bits (tf32 mma ignores low mantissa bits) ----
    #pragma unroll
    for (int i = 0; i < 16; i++) {
        int idx = tid + i * 256;
        int r = idx >> 6, c4 = idx & 63;
        uint4 u = *reinterpret_cast<const uint4*>(x + (size_t)r * HW + e0 + (c4 << 2));
        *reinterpret_cast<uint4*>(xs + r * XSTR + (c4 << 2)) = u;
    }
    for (int idx = tid; idx < 4096; idx += 256) {
        int o = idx >> 6, c = idx & 63;
        wa[o * WSTR + c] = tf32_(conv_w[idx]);
        wb[o * WSTR + c] = tf32_(val_w[idx]);
    }
    if (tid < 64) {
        kws[tid] = key_w[tid];
        float sc = val_g[tid] * rsqrtf(val_v[tid] + EPS);
        vsc[tid] = sc; vsh[tid] = val_b[tid] - val_m[tid] * sc;
    }
    __syncthreads();

    const int pixbase = wid * 32;
    float acc[16][4];

    // ================= phase A: xc conv =================
    #pragma unroll
    for (int i = 0; i < 16; i++) { acc[i][0]=0.f; acc[i][1]=0.f; acc[i][2]=0.f; acc[i][3]=0.f; }
    gemm_tile(xs, wa, acc, pixbase, g, t);

    #pragma unroll
    for (int mt = 0; mt < 4; mt++) {
        float slo = 0.f, shi = 0.f, mlo = -3.0e38f, mhi = -3.0e38f;
        #pragma unroll
        for (int nt = 0; nt < 4; nt++) {
            float c0 = acc[mt*4+nt][0], c1 = acc[mt*4+nt][1];
            float c2 = acc[mt*4+nt][2], c3 = acc[mt*4+nt][3];
            slo += c0 + c1; shi += c2 + c3;
            mlo = fmaxf(mlo, fmaxf(c0, c1));
            mhi = fmaxf(mhi, fmaxf(c2, c3));
        }
        #pragma unroll
        for (int off = 1; off < 4; off <<= 1) {
            slo += __shfl_xor_sync(0xffffffffu, slo, off);
            shi += __shfl_xor_sync(0xffffffffu, shi, off);
            mlo = fmaxf(mlo, __shfl_xor_sync(0xffffffffu, mlo, off));
            mhi = fmaxf(mhi, __shfl_xor_sync(0xffffffffu, mhi, off));
        }
        if (t == 0) {
            ps[wid * 64 + mt * 16 + g]     = slo;
            ps[wid * 64 + mt * 16 + g + 8] = shi;
            pm[wid * 64 + mt * 16 + g]     = mlo;
            pm[wid * 64 + mt * 16 + g + 8] = mhi;
        }
    }

    // ---- key conv: one pixel per thread (exact fp32 x) ----
    {
        const float* xf = reinterpret_cast<const float*>(xs);
        float ka = 0.f;
        #pragma unroll 8
        for (int c = 0; c < CC; c++) ka = fmaf(kws[c], xf[c * XSTR + tid], ka);
        float kscale = key_g[0] * rsqrtf(key_v[0] + EPS);
        float kbias = key_b[0] - key_m[0] * kscale;
        float kv = siluf_(ka * kscale + kbias);
        kk[tid] = kv;
        g_k[(size_t)(s * NN + n) * HW + e0 + tid] = kv;
    }
    __syncthreads();

    if (tid < 64) {
        float sv = 0.f, mv = -3.0e38f;
        #pragma unroll
        for (int w = 0; w < 8; w++) {
            sv += ps[w * 64 + tid];
            mv = fmaxf(mv, pm[w * 64 + tid]);
        }
        size_t b = ((size_t)(s * NN + n) * NB1 + blk) * CC + tid;
        g_psum[b] = sv; g_pmax[b] = mv;
    }
    if (wid == 2) {
        float m = kk[lane];
        #pragma unroll
        for (int i = 1; i < 8; i++) m = fmaxf(m, kk[lane + 32 * i]);
        #pragma unroll
        for (int off = 16; off; off >>= 1) m = fmaxf(m, __shfl_xor_sync(0xffffffffu, m, off));
        float z = 0.f;
        #pragma unroll
        for (int i = 0; i < 8; i++) z += fexp_(kk[lane + 32 * i] - m);
        #pragma unroll
        for (int off = 16; off; off >>= 1) z += __shfl_xor_sync(0xffffffffu, z, off);
        if (lane == 0) { int b = (s * NN + n) * NB1 + blk; g_pkm[b] = m; g_pkz[b] = z; }
    }

    // ================= phase B: val conv =================
    #pragma unroll
    for (int i = 0; i < 16; i++) { acc[i][0]=0.f; acc[i][1]=0.f; acc[i][2]=0.f; acc[i][3]=0.f; }
    gemm_tile(xs, wb, acc, pixbase, g, t);

    // direct bf16 store from fragments, channel-major [c][pix]
    __nv_bfloat16* vbase = g_val + (size_t)(s * NN + n) * CC * HW;
    #pragma unroll
    for (int mt = 0; mt < 4; mt++) {
        int o = mt * 16 + g, o2 = o + 8;
        float sc = vsc[o],  sh = vsh[o];
        float sc2 = vsc[o2], sh2 = vsh[o2];
        #pragma unroll
        for (int nt = 0; nt < 4; nt++) {
            int p = pixbase + nt * 8 + 2 * t;
            float v0 = siluf_(fmaf(acc[mt*4+nt][0], sc, sh));
            float v1 = siluf_(fmaf(acc[mt*4+nt][1], sc, sh));
            float v2 = siluf_(fmaf(acc[mt*4+nt][2], sc2, sh2));
            float v3 = siluf_(fmaf(acc[mt*4+nt][3], sc2, sh2));
            __nv_bfloat162 lo = __float22bfloat162_rn(make_float2(v0, v1));
            __nv_bfloat162 hi = __float22bfloat162_rn(make_float2(v2, v3));
            *reinterpret_cast<unsigned*>(&vbase[(size_t)o  * HW + e0 + p]) = *reinterpret_cast<unsigned*>(&lo);
            *reinterpret_cast<unsigned*>(&vbase[(size_t)o2 * HW + e0 + p]) = *reinterpret_cast<unsigned*>(&hi);
        }
    }
}

// ---------------- kernel 2.5: fea partials (self-computes key M/Z) ----------------
__global__ __launch_bounds__(256) void k25()
{
    const int s = blockIdx.z, n = blockIdx.y, ch = blockIdx.x;
    const int tid = threadIdx.x, wid = tid >> 5, lane = tid & 31;
    const int sn = s * NN + n;
    __shared__ float wk[CH25];
    __shared__ float red8[8];
    __shared__ float MZ[2];

    // key max over NB1=256 block partials (one per thread)
    const size_t kb = (size_t)sn * NB1;
    float pm_ = g_pkm[kb + tid];
    float m = pm_;
    #pragma unroll
    for (int off = 16; off; off >>= 1) m = fmaxf(m, __shfl_xor_sync(0xffffffffu, m, off));
    if (lane == 0) red8[wid] = m;
    __syncthreads();
    if (tid == 0) {
        float mm = red8[0];
        #pragma unroll
        for (int i = 1; i < 8; i++) mm = fmaxf(mm, red8[i]);
        MZ[0] = mm;
    }
    __syncthreads();
    const float M = MZ[0];
    float z = g_pkz[kb + tid] * fexp_(pm_ - M);
    #pragma unroll
    for (int off = 16; off; off >>= 1) z += __shfl_xor_sync(0xffffffffu, z, off);
    if (lane == 0) red8[wid] = z;
    __syncthreads();
    if (tid == 0) {
        float zz = red8[0];
        #pragma unroll
        for (int i = 1; i < 8; i++) zz += red8[i];
        MZ[1] = zz;
    }
    __syncthreads();
    const float invZ = __fdividef(1.f, MZ[1]);

    const int e0 = ch * CH25;
    const float* kp = g_k + (size_t)sn * HW + e0;
    for (int i = tid; i < CH25; i += 256) wk[i] = fexp_(kp[i] - M) * invZ;
    __syncthreads();

    // each warp: 8 channels; dot over 1024 pixels
    const size_t vb = (size_t)((1 - s) * NN + n) * CC * HW;
    #pragma unroll
    for (int j = 0; j < 8; j++) {
        int c = wid * 8 + j;
        const unsigned* vp = reinterpret_cast<const unsigned*>(g_val + vb + (size_t)c * HW + e0);
        float acc = 0.f;
        #pragma unroll
        for (int it = 0; it < 16; it++) {
            unsigned u = vp[it * 32 + lane];
            float2 v = __bfloat1622float2(*reinterpret_cast<__nv_bfloat162*>(&u));
            int px = it * 64 + lane * 2;
            acc = fmaf(v.x, wk[px], fmaf(v.y, wk[px + 1], acc));
        }
        #pragma unroll
        for (int off = 16; off; off >>= 1) acc += __shfl_xor_sync(0xffffffffu, acc, off);
        if (lane == 0) g_feap[((size_t)sn * NB25 + ch) * CC + c] = acc;
    }
}

// ---------------- kernel 2f: avg/mx softmax + gate (fused k2+k27) ----------------
__global__ __launch_bounds__(256) void k2f(
    const float* __restrict__ conv_b, const float* __restrict__ convb_w,
    const float* __restrict__ ln_g, const float* __restrict__ ln_b)
{
    const int n = blockIdx.x, s = blockIdx.y;
    const int tid = threadIdx.x, c = tid & 63, r = tid >> 6;
    const int sn = s * NN + n;
    __shared__ float t4[4][64];
    __shared__ float m4[4][64];
    __shared__ float mean_s[64], mx_s[64], feas[64], gv[64];
    __shared__ float mu_s, var_s;

    const size_t base1 = (size_t)sn * NB1;
    float sv = 0.f, mv = -3.0e38f;
    for (int b = r; b < NB1; b += 4) {
        sv += g_psum[(base1 + b) * CC + c];
        mv = fmaxf(mv, g_pmax[(base1 + b) * CC + c]);
    }
    t4[r][c] = sv; m4[r][c] = mv;
    __syncthreads();
    if (r == 0) {
        float sum = t4[0][c] + t4[1][c] + t4[2][c] + t4[3][c];
        float mx  = fmaxf(fmaxf(m4[0][c], m4[1][c]), fmaxf(m4[2][c], m4[3][c]));
        mean_s[c] = sum * (1.f / HW) + conv_b[c];
        mx_s[c]   = mx + conv_b[c];
    }
    __syncthreads();

    // feas = sum of NB25 feap blocks
    const size_t base25 = (size_t)sn * NB25;
    float f = 0.f;
    for (int b = r * 16; b < r * 16 + 16; b++) f += g_feap[(base25 + b) * CC + c];
    t4[r][c] = f;
    __syncthreads();
    if (r == 0) feas[c] = t4[0][c] + t4[1][c] + t4[2][c] + t4[3][c];
    __syncthreads();

    // softmax over 64 channels for avg & mx (warp 0)
    if (tid < 32) {
        float a0 = mean_s[tid], a1 = mean_s[tid + 32];
        float m1 = fmaxf(a0, a1);
        #pragma unroll
        for (int off = 16; off; off >>= 1) m1 = fmaxf(m1, __shfl_xor_sync(0xffffffffu, m1, off));
        float e0_ = fexp_(a0 - m1), e1_ = fexp_(a1 - m1);
        float zz = e0_ + e1_;
        #pragma unroll
        for (int off = 16; off; off >>= 1) zz += __shfl_xor_sync(0xffffffffu, zz, off);
        float inv = __fdividef(1.f, zz);
        g_avg[sn * CC + tid]      = e0_ * inv;
        g_avg[sn * CC + tid + 32] = e1_ * inv;

        float b0 = mx_s[tid], b1 = mx_s[tid + 32];
        float m2 = fmaxf(b0, b1);
        #pragma unroll
        for (int off = 16; off; off >>= 1) m2 = fmaxf(m2, __shfl_xor_sync(0xffffffffu, m2, off));
        float f0 = fexp_(b0 - m2), f1 = fexp_(b1 - m2);
        float z2 = f0 + f1;
        #pragma unroll
        for (int off = 16; off; off >>= 1) z2 += __shfl_xor_sync(0xffffffffu, z2, off);
        float inv2 = __fdividef(1.f, z2);
        g_mx[sn * CC + tid]      = f0 * inv2;
        g_mx[sn * CC + tid + 32] = f1 * inv2;
    }

    // gate = sigmoid(LN(feas @ convb^T))
    if (tid < 64) {
        float gacc = 0.f;
        #pragma unroll 8
        for (int j = 0; j < CC; j++) gacc = fmaf(convb_w[c * CC + j], feas[j], gacc);
        gv[c] = gacc;
    }
    __syncthreads();
    if (tid < 32) {
        float a = gv[tid] + gv[tid + 32];
        float b2 = gv[tid] * gv[tid] + gv[tid + 32] * gv[tid + 32];
        #pragma unroll
        for (int off = 16; off; off >>= 1) {
            a  += __shfl_xor_sync(0xffffffffu, a, off);
            b2 += __shfl_xor_sync(0xffffffffu, b2, off);
        }
        if (tid == 0) {
            float mu = a * (1.f / CC);
            mu_s = mu;
            var_s = b2 * (1.f / CC) - mu * mu;
        }
    }
    __syncthreads();
    if (tid < 64) {
        float d = gv[c] - mu_s;
        float zz = d * rsqrtf(var_s + EPS) * ln_g[c] + ln_b[c];
        g_gate[sn * CC + c] = sigmoidf_(zz);
    }
}

// ---------------- kernel 3: output = gate * half + me ----------------
__global__ __launch_bounds__(256) void k3(
    const float* __restrict__ rgb, const float* __restrict__ ir, float* __restrict__ out,
    const float* __restrict__ half_w,
    const float* __restrict__ half_g, const float* __restrict__ half_b,
    const float* __restrict__ half_m, const float* __restrict__ half_v)
{
    const int s = blockIdx.z, n = blockIdx.y;
    const int e0 = blockIdx.x * P3;
    const int tid = threadIdx.x;
    __shared__ float avs[64];
    __shared__ float mxs[64];
    __shared__ float gts[64];
    if (tid < 64) {
        int i = (s * NN + n) * CC + tid;
        avs[tid] = g_avg[i]; mxs[tid] = g_mx[i]; gts[tid] = g_gate[i];
    }
    __syncthreads();

    // two pixels per thread; val is channel-major bf16
    const unsigned* vp = reinterpret_cast<const unsigned*>(
        g_val + (size_t)((1 - s) * NN + n) * CC * HW);
    const size_t pix2 = (size_t)(e0 >> 1) + tid;   // u32 index of pixel pair
    float aA0 = 0.f, aA1 = 0.f, aM0 = 0.f, aM1 = 0.f;
    #pragma unroll 8
    for (int c = 0; c < CC; c++) {
        unsigned u = vp[(size_t)c * (HW / 2) + pix2];
        float2 v = __bfloat1622float2(*reinterpret_cast<__nv_bfloat162*>(&u));
        aA0 = fmaf(v.x, avs[c], aA0); aA1 = fmaf(v.y, avs[c], aA1);
        aM0 = fmaf(v.x, mxs[c], aM0); aM1 = fmaf(v.y, mxs[c], aM1);
    }
    float hs = half_g[0] * rsqrtf(half_v[0] + EPS);
    float hb = half_b[0] - half_m[0] * hs;
    float hlf0 = siluf_((half_w[0] * aA0 + half_w[1] * aM0) * hs + hb);
    float hlf1 = siluf_((half_w[0] * aA1 + half_w[1] * aM1) * hs + hb);

    const float* xme = (s == 0 ? rgb : ir) + (size_t)n * CC * HW;
    float* op = out + (size_t)(s * NN + n) * CC * HW;
    const int p0 = e0 + 2 * tid;
    #pragma unroll 8
    for (int c = 0; c < CC; c++) {
        size_t idx = (size_t)c * HW + p0;
        float2 xv = *reinterpret_cast<const float2*>(xme + idx);
        float2 ov;
        ov.x = fmaf(gts[c], hlf0, xv.x);
        ov.y = fmaf(gts[c], hlf1, xv.y);
        *reinterpret_cast<float2*>(op + idx) = ov;
    }
}

// ---------------- launch ----------------
extern "C" void kernel_launch(void* const* d_in, const int* in_sizes, int n_in,
                              void* d_out, int out_size)
{
    const float* rgb     = (const float*)d_in[0];
    const float* ir      = (const float*)d_in[1];
    const float* conv_w  = (const float*)d_in[2];
    const float* conv_b  = (const float*)d_in[3];
    const float* key_w   = (const float*)d_in[4];
    const float* key_g   = (const float*)d_in[5];
    const float* key_b   = (const float*)d_in[6];
    const float* key_m   = (const float*)d_in[7];
    const float* key_v   = (const float*)d_in[8];
    const float* val_w   = (const float*)d_in[9];
    const float* val_g   = (const float*)d_in[10];
    const float* val_b   = (const float*)d_in[11];
    const float* val_m   = (const float*)d_in[12];
    const float* val_v   = (const float*)d_in[13];
    const float* convb_w = (const float*)d_in[14];
    const float* half_w  = (const float*)d_in[15];
    const float* half_g  = (const float*)d_in[16];
    const float* half_b  = (const float*)d_in[17];
    const float* half_m  = (const float*)d_in[18];
    const float* half_v  = (const float*)d_in[19];
    const float* ln_g    = (const float*)d_in[20];
    const float* ln_b    = (const float*)d_in[21];
    float* out = (float*)d_out;

    const size_t smem1 = SM1_FLOATS * sizeof(float);   // 110336 B
    cudaFuncSetAttribute(k1, cudaFuncAttributeMaxDynamicSharedMemorySize, (int)smem1);

    k1<<<dim3(NB1, NN, 2), 256, smem1>>>(rgb, ir, conv_w, val_w, key_w,
                                         key_g, key_b, key_m, key_v,
                                         val_g, val_b, val_m, val_v);
    k25<<<dim3(NB25, NN, 2), 256>>>();
    k2f<<<dim3(NN, 2), 256>>>(conv_b, convb_w, ln_g, ln_b);
    k3<<<dim3(NB3, NN, 2), 256>>>(rgb, ir, out, half_w, half_g, half_b, half_m, half_v);
}